// round 2
// baseline (speedup 1.0000x reference)
#include <cuda_runtime.h>
#include <cstdint>

#define TN        128
#define NTHREADS  256

typedef unsigned long long u64;

__device__ __forceinline__ u64 pack2(float lo, float hi) {
    u64 r; asm("mov.b64 %0,{%1,%2};" : "=l"(r) : "f"(lo), "f"(hi)); return r;
}
__device__ __forceinline__ float2 unpk(u64 v) {
    float2 f; asm("mov.b64 {%0,%1},%2;" : "=f"(f.x), "=f"(f.y) : "l"(v)); return f;
}
__device__ __forceinline__ u64 fma2(u64 a, u64 b, u64 c) {
    u64 d; asm("fma.rn.f32x2 %0,%1,%2,%3;" : "=l"(d) : "l"(a), "l"(b), "l"(c)); return d;
}
__device__ __forceinline__ u64 mul2(u64 a, u64 b) {
    u64 d; asm("mul.rn.f32x2 %0,%1,%2;" : "=l"(d) : "l"(a), "l"(b)); return d;
}

// ---- shared memory layout (float offsets) ----
#define OFF_G    0                         // 32768 floats (G, c contiguous)
#define OFF_P0   32768                     // P0 scalar [128][33]   = 4224
#define OFF_P1D  36992                     // P1 dup f32x2 [128][33] f2 = 8448 floats
#define OFF_R    45440                     // R scalar  [128][33]   = 4224
#define OFF_SCR  49664
#define OFF_XS   OFF_SCR                   // XsT [32 i][130 n] = 4160
#define OFF_WD   (OFF_SCR + 32*130)        // Wdup f2 [32 i][33 r] = 2112 floats
#define OFF_UT   OFF_SCR                   // Ut [32 c][258 o] = 8256 (phase 3)
#define SMEM_FLOATS (OFF_SCR + 32*258)     // 57920
#define SMEM_BYTES  (SMEM_FLOATS * 4)      // 231680

__global__ __launch_bounds__(NTHREADS, 1)
void hosvd_kernel(const float* __restrict__ X,    // [N][2][256]
                  const float* __restrict__ Gg,   // [32][32][32]
                  const float* __restrict__ Uw,   // [2][32][256]
                  const float* __restrict__ Ub,   // [2][32]
                  const float* __restrict__ Uo,   // [256][32]
                  float* __restrict__ out,        // [N][256]
                  int nNodes)
{
    extern __shared__ float sm[];
    const int tid  = threadIdx.x;
    const int base = blockIdx.x * TN;
    const int ng   = tid >> 3;      // 0..31  node group (4 nodes = 2 pairs)
    const int rg   = tid & 7;       // 0..7   output group (4 cols = 2 pairs)
    const int ng4  = ng * 4;
    const int rg4  = rg * 4;

    // ---- load G into shared (coalesced float4 copy) ----
    {
        const float4* g4 = reinterpret_cast<const float4*>(Gg);
        float4* s4 = reinterpret_cast<float4*>(sm + OFF_G);
        #pragma unroll
        for (int k = 0; k < 32; k++)
            s4[tid + NTHREADS * k] = g4[tid + NTHREADS * k];
    }

    // ================= Phase 1: projections =================
    for (int d = 0; d < 2; d++) {
        u64 acc[2][4];
        #pragma unroll
        for (int jp = 0; jp < 2; jp++)
            #pragma unroll
            for (int k = 0; k < 4; k++) acc[jp][k] = 0ull;

        for (int chunk = 0; chunk < 8; chunk++) {
            const int i0 = chunk * 32;
            __syncthreads();   // protect scratch from previous readers
            // stage X chunk transposed: XsT[i][n], 32 i x 128 n
            #pragma unroll
            for (int t = 0; t < 4; t++) {
                int idx = tid + NTHREADS * t;   // 0..1023 float4s
                int n_l = idx >> 3;
                int i4  = (idx & 7) << 2;
                int n   = base + n_l;
                float4 v = make_float4(0.f, 0.f, 0.f, 0.f);
                if (n < nNodes)
                    v = *reinterpret_cast<const float4*>(X + (size_t)n * 512 + d * 256 + i0 + i4);
                sm[OFF_XS + (i4 + 0) * 130 + n_l] = v.x;
                sm[OFF_XS + (i4 + 1) * 130 + n_l] = v.y;
                sm[OFF_XS + (i4 + 2) * 130 + n_l] = v.z;
                sm[OFF_XS + (i4 + 3) * 130 + n_l] = v.w;
            }
            // stage W chunk duplicated: Wdup[i][perm(r)] = (w,w)
            {
                int r  = tid >> 3;              // 0..31
                int i4 = (tid & 7) << 2;
                float4 v = *reinterpret_cast<const float4*>(Uw + d * 8192 + r * 256 + i0 + i4);
                int rr = r + (r >> 4);          // bank-spread permutation
                u64* wd = reinterpret_cast<u64*>(sm + OFF_WD);
                wd[(i4 + 0) * 33 + rr] = pack2(v.x, v.x);
                wd[(i4 + 1) * 33 + rr] = pack2(v.y, v.y);
                wd[(i4 + 2) * 33 + rr] = pack2(v.z, v.z);
                wd[(i4 + 3) * 33 + rr] = pack2(v.w, v.w);
            }
            __syncthreads();
            const u64* wd = reinterpret_cast<const u64*>(sm + OFF_WD);
            const int rrb = rg4 + (rg >> 2);    // perm base for this thread
            #pragma unroll 8
            for (int i = 0; i < 32; i++) {
                u64 xp0 = *reinterpret_cast<const u64*>(sm + OFF_XS + i * 130 + ng4);
                u64 xp1 = *reinterpret_cast<const u64*>(sm + OFF_XS + i * 130 + ng4 + 2);
                #pragma unroll
                for (int k = 0; k < 4; k++) {
                    u64 w = wd[i * 33 + rrb + k];
                    acc[0][k] = fma2(xp0, w, acc[0][k]);
                    acc[1][k] = fma2(xp1, w, acc[1][k]);
                }
            }
        }
        // store P with bias
        #pragma unroll
        for (int k = 0; k < 4; k++) {
            float b = Ub[d * 32 + rg4 + k];
            #pragma unroll
            for (int jp = 0; jp < 2; jp++) {
                float2 v = unpk(acc[jp][k]);
                int n0 = ng4 + 2 * jp;
                if (d == 0) {
                    sm[OFF_P0 + (n0 + 0) * 33 + rg4 + k] = v.x + b;
                    sm[OFF_P0 + (n0 + 1) * 33 + rg4 + k] = v.y + b;
                } else {
                    u64* p1 = reinterpret_cast<u64*>(sm + OFF_P1D);
                    float a0 = v.x + b, a1 = v.y + b;
                    p1[(n0 + 0) * 33 + rg4 + k] = pack2(a0, a0);
                    p1[(n0 + 1) * 33 + rg4 + k] = pack2(a1, a1);
                }
            }
        }
    }
    __syncthreads();   // P visible; scratch free

    // ---- stage transposed U_out: Ut[c][o], stride 258 ----
    #pragma unroll
    for (int t = 0; t < 8; t++) {
        int idx = tid + NTHREADS * t;   // 0..2047 float4s
        int o   = idx >> 3;
        int c0  = (idx & 7) << 2;
        float4 v = *reinterpret_cast<const float4*>(Uo + o * 32 + c0);
        sm[OFF_UT + (c0 + 0) * 258 + o] = v.x;
        sm[OFF_UT + (c0 + 1) * 258 + o] = v.y;
        sm[OFF_UT + (c0 + 2) * 258 + o] = v.z;
        sm[OFF_UT + (c0 + 3) * 258 + o] = v.w;
    }

    // ================= Phase 2: Tucker core (c-pair packed) =================
    {
        u64 acc[4][2];
        #pragma unroll
        for (int j = 0; j < 4; j++) { acc[j][0] = 0ull; acc[j][1] = 0ull; }

        const u64* p1 = reinterpret_cast<const u64*>(sm + OFF_P1D);
        for (int a0 = 0; a0 < 32; a0 += 4) {
            u64 p0d[4][4];
            #pragma unroll
            for (int j = 0; j < 4; j++)
                #pragma unroll
                for (int a = 0; a < 4; a++) {
                    float s = sm[OFF_P0 + (ng4 + j) * 33 + a0 + a];
                    p0d[j][a] = pack2(s, s);
                }
            #pragma unroll 4
            for (int b = 0; b < 32; b++) {
                u64 p1d[4];
                #pragma unroll
                for (int j = 0; j < 4; j++)
                    p1d[j] = p1[(ng4 + j) * 33 + b];
                #pragma unroll
                for (int a = 0; a < 4; a++) {
                    const float* g = sm + OFF_G + (a0 + a) * 1024 + b * 32 + rg4;
                    u64 g0 = *reinterpret_cast<const u64*>(g);
                    u64 g1 = *reinterpret_cast<const u64*>(g + 2);
                    #pragma unroll
                    for (int j = 0; j < 4; j++) {
                        u64 zp = mul2(p0d[j][a], p1d[j]);
                        acc[j][0] = fma2(zp, g0, acc[j][0]);
                        acc[j][1] = fma2(zp, g1, acc[j][1]);
                    }
                }
            }
        }
        #pragma unroll
        for (int j = 0; j < 4; j++)
            #pragma unroll
            for (int kp = 0; kp < 2; kp++) {
                float2 v = unpk(acc[j][kp]);
                sm[OFF_R + (ng4 + j) * 33 + rg4 + 2 * kp + 0] = v.x;
                sm[OFF_R + (ng4 + j) * 33 + rg4 + 2 * kp + 1] = v.y;
            }
    }
    __syncthreads();   // R + Ut visible

    // ================= Phase 3: output (o-pair packed) =================
    for (int half = 0; half < 2; half++) {
        u64 acc[4][4][2];
        #pragma unroll
        for (int j = 0; j < 4; j++)
            #pragma unroll
            for (int k = 0; k < 4; k++) { acc[j][k][0] = 0ull; acc[j][k][1] = 0ull; }

        #pragma unroll 4
        for (int c = 0; c < 32; c++) {
            u64 rv[4];
            #pragma unroll
            for (int j = 0; j < 4; j++) {
                float s = sm[OFF_R + (ng4 + j) * 33 + c];
                rv[j] = pack2(s, s);
            }
            const float* u = sm + OFF_UT + c * 258 + half * 128 + rg4;
            #pragma unroll
            for (int k = 0; k < 4; k++) {
                u64 u0 = *reinterpret_cast<const u64*>(u + k * 32);
                u64 u1 = *reinterpret_cast<const u64*>(u + k * 32 + 2);
                #pragma unroll
                for (int j = 0; j < 4; j++) {
                    acc[j][k][0] = fma2(rv[j], u0, acc[j][k][0]);
                    acc[j][k][1] = fma2(rv[j], u1, acc[j][k][1]);
                }
            }
        }
        #pragma unroll
        for (int j = 0; j < 4; j++) {
            int n = base + ng4 + j;
            if (n < nNodes) {
                float* op = out + (size_t)n * 256 + half * 128 + rg4;
                #pragma unroll
                for (int k = 0; k < 4; k++) {
                    float2 v0 = unpk(acc[j][k][0]);
                    float2 v1 = unpk(acc[j][k][1]);
                    *reinterpret_cast<float2*>(op + k * 32)     = v0;
                    *reinterpret_cast<float2*>(op + k * 32 + 2) = v1;
                }
            }
        }
    }
}

extern "C" void kernel_launch(void* const* d_in, const int* in_sizes, int n_in,
                              void* d_out, int out_size)
{
    const float* X  = (const float*)d_in[0];   // neighbour_states [N,2,256]
    const float* Gg = (const float*)d_in[1];   // G [32,32,32]
    const float* Uw = (const float*)d_in[2];   // U_w [2,32,256]
    const float* Ub = (const float*)d_in[3];   // U_b [2,32]
    const float* Uo = (const float*)d_in[4];   // U_out [256,32]
    float* outp = (float*)d_out;

    int nNodes = in_sizes[0] / 512;            // 2*256 floats per node

    cudaFuncSetAttribute(hosvd_kernel,
                         cudaFuncAttributeMaxDynamicSharedMemorySize, SMEM_BYTES);

    int grid = (nNodes + TN - 1) / TN;
    hosvd_kernel<<<grid, NTHREADS, SMEM_BYTES>>>(X, Gg, Uw, Ub, Uo, outp, nNodes);
}

// round 4
// speedup vs baseline: 1.6493x; 1.6493x over previous
#include <cuda_runtime.h>
#include <cstdint>

typedef uint32_t u32;

#define TN   128
#define NTH  256

// ---------- global fp16-split weight images (written by prep kernel) ----------
// UWS: [d][sp][32 r][264 halves]  = 67584 B
// GS : [sp][32 a][32 c][40 halves] = 163840 B   (element = G[a][b][c] at [..][c][b])
// UOS: [sp][256 o][40 halves]      = 40960 B
__device__ u32 g_UWS[16896];
__device__ u32 g_GS[40960];
__device__ u32 g_UOS[10240];

// ---------- smem byte offsets ----------
#define OFF_P    0                 // P fp32 [128][68]           34816 B
#define OFF_P1S  34816             // p1 split [2][128][40] h    20480 B
#define OFF_RS   34816             // (reuse for R split, phase3)
#define OFF_G    55296             // GS image                  163840 B
#define OFF_UW   55296             // UWS image (phase1 alias)   67584 B
#define OFF_UO   55296             // UOS image (phase3 alias)   40960 B
#define OFF_OB   96256             // out roundtrip [128][132]f  67584 B
#define OFF_XS   122880            // X split [2][128][72] h     36864 B
#define OFF_UB   219136            // bias 64 floats               256 B
#define SMEM_TOTAL 219392

// pack two f32 -> f16x2 (flo -> bits[15:0])
__device__ __forceinline__ u32 pkh(float flo, float fhi) {
    u32 r; asm("cvt.rn.f16x2.f32 %0,%1,%2;" : "=r"(r) : "f"(fhi), "f"(flo)); return r;
}
__device__ __forceinline__ void uph(u32 p, float& flo, float& fhi) {
    asm("{.reg .f16 a,b; mov.b32 {a,b},%2; cvt.f32.f16 %0,a; cvt.f32.f16 %1,b;}"
        : "=f"(flo), "=f"(fhi) : "r"(p));
}
__device__ __forceinline__ void split2h(float x, float y, u32& hi, u32& lo) {
    hi = pkh(x, y);
    float hx, hy; uph(hi, hx, hy);
    lo = pkh(x - hx, y - hy);
}
__device__ __forceinline__ void mma16816(float4& d, u32 a0, u32 a1, u32 a2, u32 a3,
                                         u32 b0, u32 b1) {
    asm volatile(
        "mma.sync.aligned.m16n8k16.row.col.f32.f16.f16.f32 "
        "{%0,%1,%2,%3},{%4,%5,%6,%7},{%8,%9},{%0,%1,%2,%3};"
        : "+f"(d.x), "+f"(d.y), "+f"(d.z), "+f"(d.w)
        : "r"(a0), "r"(a1), "r"(a2), "r"(a3), "r"(b0), "r"(b1));
}

// ================= prep: split weights to fp16 hi/lo global images =================
__global__ void prep_kernel(const float* __restrict__ Uw,
                            const float* __restrict__ Gg,
                            const float* __restrict__ Uo)
{
    for (int task = blockIdx.x * blockDim.x + threadIdx.x; task < 28672;
         task += gridDim.x * blockDim.x) {
        if (task < 8192) {                       // UWS: d(2) x r(32) x ip(128)
            int d = task >> 12, r = (task >> 7) & 31, ip = task & 127;
            float x0 = Uw[d * 8192 + r * 256 + 2 * ip];
            float x1 = Uw[d * 8192 + r * 256 + 2 * ip + 1];
            u32 hi, lo; split2h(x0, x1, hi, lo);
            g_UWS[((d * 2 + 0) * 32 + r) * 132 + ip] = hi;
            g_UWS[((d * 2 + 1) * 32 + r) * 132 + ip] = lo;
        } else if (task < 24576) {               // GS: a(32) x c(32) x bp(16)
            int t = task - 8192;
            int a = t >> 9, c = (t >> 4) & 31, bp = t & 15;
            float x0 = Gg[a * 1024 + (2 * bp) * 32 + c];
            float x1 = Gg[a * 1024 + (2 * bp + 1) * 32 + c];
            u32 hi, lo; split2h(x0, x1, hi, lo);
            g_GS[((0 * 32 + a) * 32 + c) * 20 + bp] = hi;
            g_GS[((1 * 32 + a) * 32 + c) * 20 + bp] = lo;
        } else {                                 // UOS: o(256) x cp(16)
            int t = task - 24576;
            int o = t >> 4, cp = t & 15;
            float x0 = Uo[o * 32 + 2 * cp];
            float x1 = Uo[o * 32 + 2 * cp + 1];
            u32 hi, lo; split2h(x0, x1, hi, lo);
            g_UOS[(0 * 256 + o) * 20 + cp] = hi;
            g_UOS[(1 * 256 + o) * 20 + cp] = lo;
        }
    }
}

// ================= main =================
__global__ __launch_bounds__(NTH, 1)
void hosvd_mma(const float* __restrict__ X,    // [N][2][256]
               const float* __restrict__ Ub,   // [2][32]
               float* __restrict__ out,        // [N][256]
               int nN)
{
    extern __shared__ char sm[];
    const int tid = threadIdx.x;
    const int q   = tid & 3;                       // quad in warp
    const int r0  = (tid >> 5) * 16 + ((tid & 31) >> 2);  // fragment row (m)
    const int base = blockIdx.x * TN;

    // ---- stage Uw image + bias ----
    {
        const uint4* src = (const uint4*)g_UWS;
        for (int i = tid; i < 4224; i += NTH)
            *(uint4*)(sm + OFF_UW + i * 16) = src[i];
        if (tid < 64) *(float*)(sm + OFF_UB + tid * 4) = Ub[tid];
    }
    __syncthreads();

    // ================= Phase 1: P = [X_d @ Uw_d^T]  (cols d*32+r) =================
    float4 acc1[8];
    #pragma unroll
    for (int fs = 0; fs < 8; fs++) acc1[fs] = make_float4(0.f, 0.f, 0.f, 0.f);

    for (int d = 0; d < 2; d++) {
        for (int ch = 0; ch < 4; ch++) {
            const int c4 = ch * 64;
            __syncthreads();
            // stage X chunk split: XS[sp][128 n][72 halves]
            #pragma unroll
            for (int g = 0; g < 8; g++) {
                int fid = tid + NTH * g;              // 0..2047
                int row = fid >> 4, f4 = fid & 15;
                int n = base + row;
                float4 v = make_float4(0.f, 0.f, 0.f, 0.f);
                if (n < nN)
                    v = *(const float4*)(X + (size_t)n * 512 + d * 256 + c4 + f4 * 4);
                u32 h0, l0, h1, l1;
                split2h(v.x, v.y, h0, l0);
                split2h(v.z, v.w, h1, l1);
                *(uint2*)(sm + OFF_XS + 0 * 18432 + row * 144 + f4 * 8) = make_uint2(h0, h1);
                *(uint2*)(sm + OFF_XS + 1 * 18432 + row * 144 + f4 * 8) = make_uint2(l0, l1);
            }
            __syncthreads();
            #pragma unroll
            for (int ks = 0; ks < 4; ks++) {
                const int kk = ks * 16 + q * 2;
                u32 xh[4], xl[4];
                xh[0] = *(u32*)(sm + OFF_XS + ((r0    ) * 72 + kk    ) * 2);
                xh[1] = *(u32*)(sm + OFF_XS + ((r0 + 8) * 72 + kk    ) * 2);
                xh[2] = *(u32*)(sm + OFF_XS + ((r0    ) * 72 + kk + 8) * 2);
                xh[3] = *(u32*)(sm + OFF_XS + ((r0 + 8) * 72 + kk + 8) * 2);
                xl[0] = *(u32*)(sm + OFF_XS + 18432 + ((r0    ) * 72 + kk    ) * 2);
                xl[1] = *(u32*)(sm + OFF_XS + 18432 + ((r0 + 8) * 72 + kk    ) * 2);
                xl[2] = *(u32*)(sm + OFF_XS + 18432 + ((r0    ) * 72 + kk + 8) * 2);
                xl[3] = *(u32*)(sm + OFF_XS + 18432 + ((r0 + 8) * 72 + kk + 8) * 2);
                #pragma unroll
                for (int nt = 0; nt < 4; nt++) {
                    int ncol = nt * 8 + ((tid & 31) >> 2);
                    int bi = ((d * 2 + 0) * 32 + ncol) * 264 + c4 + kk;
                    int li = ((d * 2 + 1) * 32 + ncol) * 264 + c4 + kk;
                    u32 bh0 = *(u32*)(sm + OFF_UW + bi * 2);
                    u32 bh1 = *(u32*)(sm + OFF_UW + (bi + 8) * 2);
                    u32 bl0 = *(u32*)(sm + OFF_UW + li * 2);
                    u32 bl1 = *(u32*)(sm + OFF_UW + (li + 8) * 2);
                    mma16816(acc1[d * 4 + nt], xh[0], xh[1], xh[2], xh[3], bh0, bh1);
                    mma16816(acc1[d * 4 + nt], xl[0], xl[1], xl[2], xl[3], bh0, bh1);
                    mma16816(acc1[d * 4 + nt], xh[0], xh[1], xh[2], xh[3], bl0, bl1);
                }
            }
        }
    }
    __syncthreads();   // phase1 done; UW/XS regions free

    // ---- P epilogue: +bias -> P fp32 [128][68]; cols 32..63 also split -> P1S ----
    {
        float* Pf = (float*)(sm + OFF_P);
        #pragma unroll
        for (int fs = 0; fs < 8; fs++) {
            int c0 = fs * 8 + q * 2;
            float bx = *(float*)(sm + OFF_UB + c0 * 4);
            float by = *(float*)(sm + OFF_UB + (c0 + 1) * 4);
            float px0 = acc1[fs].x + bx, py0 = acc1[fs].y + by;
            float px1 = acc1[fs].z + bx, py1 = acc1[fs].w + by;
            Pf[r0 * 68 + c0] = px0;       Pf[r0 * 68 + c0 + 1] = py0;
            Pf[(r0 + 8) * 68 + c0] = px1; Pf[(r0 + 8) * 68 + c0 + 1] = py1;
            if (c0 >= 32) {
                int cc = c0 - 32;
                u32 hi, lo;
                split2h(px0, py0, hi, lo);
                *(u32*)(sm + OFF_P1S + 0 * 10240 + (r0 * 40 + cc) * 2) = hi;
                *(u32*)(sm + OFF_P1S + 1 * 10240 + (r0 * 40 + cc) * 2) = lo;
                split2h(px1, py1, hi, lo);
                *(u32*)(sm + OFF_P1S + 0 * 10240 + ((r0 + 8) * 40 + cc) * 2) = hi;
                *(u32*)(sm + OFF_P1S + 1 * 10240 + ((r0 + 8) * 40 + cc) * 2) = lo;
            }
        }
        // stage G image (overwrites UW/XS region)
        const uint4* src = (const uint4*)g_GS;
        for (int i = tid; i < 10240; i += NTH)
            *(uint4*)(sm + OFF_G + i * 16) = src[i];
    }
    __syncthreads();

    // ================= Phase 2: r[n,c] = sum_a p0[n,a] * (p1 @ G[a]^T) =================
    float4 acc2[4];
    #pragma unroll
    for (int nt = 0; nt < 4; nt++) acc2[nt] = make_float4(0.f, 0.f, 0.f, 0.f);
    {
        const float* Pf = (const float*)(sm + OFF_P);
        u32 pH[2][4], pL[2][4];
        #pragma unroll
        for (int ks = 0; ks < 2; ks++) {
            const int kk = ks * 16 + q * 2;
            pH[ks][0] = *(u32*)(sm + OFF_P1S + ((r0    ) * 40 + kk    ) * 2);
            pH[ks][1] = *(u32*)(sm + OFF_P1S + ((r0 + 8) * 40 + kk    ) * 2);
            pH[ks][2] = *(u32*)(sm + OFF_P1S + ((r0    ) * 40 + kk + 8) * 2);
            pH[ks][3] = *(u32*)(sm + OFF_P1S + ((r0 + 8) * 40 + kk + 8) * 2);
            pL[ks][0] = *(u32*)(sm + OFF_P1S + 10240 + ((r0    ) * 40 + kk    ) * 2);
            pL[ks][1] = *(u32*)(sm + OFF_P1S + 10240 + ((r0 + 8) * 40 + kk    ) * 2);
            pL[ks][2] = *(u32*)(sm + OFF_P1S + 10240 + ((r0    ) * 40 + kk + 8) * 2);
            pL[ks][3] = *(u32*)(sm + OFF_P1S + 10240 + ((r0 + 8) * 40 + kk + 8) * 2);
        }
        for (int a = 0; a < 32; a++) {
            float s0 = Pf[r0 * 68 + a];
            float s1 = Pf[(r0 + 8) * 68 + a];
            #pragma unroll
            for (int nt = 0; nt < 4; nt++) {
                int cgl = nt * 8 + ((tid & 31) >> 2);
                float4 t4 = make_float4(0.f, 0.f, 0.f, 0.f);
                #pragma unroll
                for (int ks = 0; ks < 2; ks++) {
                    const int kk = ks * 16 + q * 2;
                    int gi = (a * 32 + cgl) * 40 + kk;
                    u32 gh0 = *(u32*)(sm + OFF_G + gi * 2);
                    u32 gh1 = *(u32*)(sm + OFF_G + (gi + 8) * 2);
                    u32 gl0 = *(u32*)(sm + OFF_G + 81920 + gi * 2);
                    u32 gl1 = *(u32*)(sm + OFF_G + 81920 + (gi + 8) * 2);
                    mma16816(t4, pH[ks][0], pH[ks][1], pH[ks][2], pH[ks][3], gh0, gh1);
                    mma16816(t4, pL[ks][0], pL[ks][1], pL[ks][2], pL[ks][3], gh0, gh1);
                    mma16816(t4, pH[ks][0], pH[ks][1], pH[ks][2], pH[ks][3], gl0, gl1);
                }
                acc2[nt].x += s0 * t4.x;
                acc2[nt].y += s0 * t4.y;
                acc2[nt].z += s1 * t4.z;
                acc2[nt].w += s1 * t4.w;
            }
        }
    }
    __syncthreads();   // phase2 done; P1S & G regions free

    // ---- R epilogue: split -> RS [2][128][40]; stage Uo image ----
    #pragma unroll
    for (int nt = 0; nt < 4; nt++) {
        int c0 = nt * 8 + q * 2;
        u32 hi, lo;
        split2h(acc2[nt].x, acc2[nt].y, hi, lo);
        *(u32*)(sm + OFF_RS + 0 * 10240 + (r0 * 40 + c0) * 2) = hi;
        *(u32*)(sm + OFF_RS + 1 * 10240 + (r0 * 40 + c0) * 2) = lo;
        split2h(acc2[nt].z, acc2[nt].w, hi, lo);
        *(u32*)(sm + OFF_RS + 0 * 10240 + ((r0 + 8) * 40 + c0) * 2) = hi;
        *(u32*)(sm + OFF_RS + 1 * 10240 + ((r0 + 8) * 40 + c0) * 2) = lo;
    }
    {
        const uint4* src = (const uint4*)g_UOS;
        for (int i = tid; i < 2560; i += NTH)
            *(uint4*)(sm + OFF_UO + i * 16) = src[i];
    }
    __syncthreads();

    // ================= Phase 3: Out = R @ Uo^T  (N=256, two halves) =================
    u32 rH[2][4], rL[2][4];
    #pragma unroll
    for (int ks = 0; ks < 2; ks++) {
        const int kk = ks * 16 + q * 2;
        rH[ks][0] = *(u32*)(sm + OFF_RS + ((r0    ) * 40 + kk    ) * 2);
        rH[ks][1] = *(u32*)(sm + OFF_RS + ((r0 + 8) * 40 + kk    ) * 2);
        rH[ks][2] = *(u32*)(sm + OFF_RS + ((r0    ) * 40 + kk + 8) * 2);
        rH[ks][3] = *(u32*)(sm + OFF_RS + ((r0 + 8) * 40 + kk + 8) * 2);
        rL[ks][0] = *(u32*)(sm + OFF_RS + 10240 + ((r0    ) * 40 + kk    ) * 2);
        rL[ks][1] = *(u32*)(sm + OFF_RS + 10240 + ((r0 + 8) * 40 + kk    ) * 2);
        rL[ks][2] = *(u32*)(sm + OFF_RS + 10240 + ((r0    ) * 40 + kk + 8) * 2);
        rL[ks][3] = *(u32*)(sm + OFF_RS + 10240 + ((r0 + 8) * 40 + kk + 8) * 2);
    }

    for (int h = 0; h < 2; h++) {
        float4 acc3[16];
        #pragma unroll
        for (int nt = 0; nt < 16; nt++) acc3[nt] = make_float4(0.f, 0.f, 0.f, 0.f);
        #pragma unroll 4
        for (int nt = 0; nt < 16; nt++) {
            int o = h * 128 + nt * 8 + ((tid & 31) >> 2);
            #pragma unroll
            for (int ks = 0; ks < 2; ks++) {
                const int kk = ks * 16 + q * 2;
                int ui = o * 40 + kk;
                u32 uh0 = *(u32*)(sm + OFF_UO + ui * 2);
                u32 uh1 = *(u32*)(sm + OFF_UO + (ui + 8) * 2);
                u32 ul0 = *(u32*)(sm + OFF_UO + 20480 + ui * 2);
                u32 ul1 = *(u32*)(sm + OFF_UO + 20480 + (ui + 8) * 2);
                mma16816(acc3[nt], rH[ks][0], rH[ks][1], rH[ks][2], rH[ks][3], uh0, uh1);
                mma16816(acc3[nt], rL[ks][0], rL[ks][1], rL[ks][2], rL[ks][3], uh0, uh1);
                mma16816(acc3[nt], rH[ks][0], rH[ks][1], rH[ks][2], rH[ks][3], ul0, ul1);
            }
        }
        // roundtrip through smem for coalesced STG
        float* ob = (float*)(sm + OFF_OB);
        #pragma unroll
        for (int nt = 0; nt < 16; nt++) {
            int c0 = nt * 8 + q * 2;
            ob[r0 * 132 + c0] = acc3[nt].x;       ob[r0 * 132 + c0 + 1] = acc3[nt].y;
            ob[(r0 + 8) * 132 + c0] = acc3[nt].z; ob[(r0 + 8) * 132 + c0 + 1] = acc3[nt].w;
        }
        __syncthreads();
        #pragma unroll 4
        for (int pass = 0; pass < 16; pass++) {
            int row = pass * 8 + (tid >> 5);
            int c4  = (tid & 31) * 4;
            int n = base + row;
            if (n < nN) {
                float4 v = *(float4*)(ob + row * 132 + c4);
                *(float4*)(out + (size_t)n * 256 + h * 128 + c4) = v;
            }
        }
        __syncthreads();
    }
}

extern "C" void kernel_launch(void* const* d_in, const int* in_sizes, int n_in,
                              void* d_out, int out_size)
{
    const float* X  = (const float*)d_in[0];   // neighbour_states
    const float* Gg = (const float*)d_in[1];   // G
    const float* Uw = (const float*)d_in[2];   // U_w
    const float* Ub = (const float*)d_in[3];   // U_b
    const float* Uo = (const float*)d_in[4];   // U_out
    float* outp = (float*)d_out;

    int nNodes = in_sizes[0] / 512;

    prep_kernel<<<32, 256>>>(Uw, Gg, Uo);

    cudaFuncSetAttribute(hosvd_mma,
                         cudaFuncAttributeMaxDynamicSharedMemorySize, SMEM_TOTAL);
    int grid = (nNodes + TN - 1) / TN;
    hosvd_mma<<<grid, NTH, SMEM_TOTAL>>>(X, Ub, outp, nNodes);
}

// round 5
// speedup vs baseline: 2.4890x; 1.5091x over previous
#include <cuda_runtime.h>
#include <cstdint>

typedef uint32_t u32;

#define TN   128
#define NTH  256

// ---------- global fp16-split weight images (written by prep kernel) ----------
// UWS: [d][sp][32 r][264 halves]   -> u32[16896]
// GS : [sp][32 a][32 c][40 halves] -> u32[40960]
// UOS: [sp][256 o][40 halves]      -> u32[10240]
__device__ __align__(16) u32 g_UWS[16896];
__device__ __align__(16) u32 g_GS[40960];
__device__ __align__(16) u32 g_UOS[10240];

// ---------- smem byte offsets ----------
#define OFF_UB   0            // 256 B (64 floats bias)
#define OFF_P0   256          // fp32 [128][33] = 16896 -> ends 17152
#define OFF_P1S  17152        // [2][128][40]h = 20480 -> ends 37632
#define OFF_RS   17152        // alias (phase 3)
#define OFF_SCR  37632
#define OFF_UW   OFF_SCR      // per-d Uw image: 33792 -> 71424
#define OFF_XS   71424        // X split [2][128][72]h = 36864 -> 108288
#define OFF_GB   OFF_SCR      // G pingpong 2 x 20480 = 40960 -> 78592
#define OFF_UO   OFF_SCR      // Uo image 40960 -> 78592
#define SMEM_TOTAL 108288

__device__ __forceinline__ u32 s2u(const void* p) {
    u32 a; asm("{.reg .u64 t; cvta.to.shared.u64 t,%1; cvt.u32.u64 %0,t;}" : "=r"(a) : "l"(p));
    return a;
}
__device__ __forceinline__ void cpa16(u32 dst, const void* src) {
    asm volatile("cp.async.ca.shared.global [%0],[%1],16;" :: "r"(dst), "l"(src));
}
#define CPA_COMMIT asm volatile("cp.async.commit_group;" ::: "memory")
#define CPA_WAIT0  asm volatile("cp.async.wait_group 0;" ::: "memory")

// pack two f32 -> f16x2 (flo -> bits[15:0])
__device__ __forceinline__ u32 pkh(float flo, float fhi) {
    u32 r; asm("cvt.rn.f16x2.f32 %0,%1,%2;" : "=r"(r) : "f"(fhi), "f"(flo)); return r;
}
__device__ __forceinline__ void uph(u32 p, float& flo, float& fhi) {
    asm("{.reg .f16 a,b; mov.b32 {a,b},%2; cvt.f32.f16 %0,a; cvt.f32.f16 %1,b;}"
        : "=f"(flo), "=f"(fhi) : "r"(p));
}
__device__ __forceinline__ void split2h(float x, float y, u32& hi, u32& lo) {
    hi = pkh(x, y);
    float hx, hy; uph(hi, hx, hy);
    lo = pkh(x - hx, y - hy);
}
__device__ __forceinline__ void mma16816(float4& d, u32 a0, u32 a1, u32 a2, u32 a3,
                                         u32 b0, u32 b1) {
    asm volatile(
        "mma.sync.aligned.m16n8k16.row.col.f32.f16.f16.f32 "
        "{%0,%1,%2,%3},{%4,%5,%6,%7},{%8,%9},{%0,%1,%2,%3};"
        : "+f"(d.x), "+f"(d.y), "+f"(d.z), "+f"(d.w)
        : "r"(a0), "r"(a1), "r"(a2), "r"(a3), "r"(b0), "r"(b1));
}

// ================= prep: split weights to fp16 hi/lo global images =================
__global__ void prep_kernel(const float* __restrict__ Uw,
                            const float* __restrict__ Gg,
                            const float* __restrict__ Uo)
{
    for (int task = blockIdx.x * blockDim.x + threadIdx.x; task < 28672;
         task += gridDim.x * blockDim.x) {
        if (task < 8192) {                       // UWS: d(2) x r(32) x ip(128)
            int d = task >> 12, r = (task >> 7) & 31, ip = task & 127;
            float x0 = Uw[d * 8192 + r * 256 + 2 * ip];
            float x1 = Uw[d * 8192 + r * 256 + 2 * ip + 1];
            u32 hi, lo; split2h(x0, x1, hi, lo);
            g_UWS[((d * 2 + 0) * 32 + r) * 132 + ip] = hi;
            g_UWS[((d * 2 + 1) * 32 + r) * 132 + ip] = lo;
        } else if (task < 24576) {               // GS: a(32) x c(32) x bp(16)
            int t = task - 8192;
            int a = t >> 9, c = (t >> 4) & 31, bp = t & 15;
            float x0 = Gg[a * 1024 + (2 * bp) * 32 + c];
            float x1 = Gg[a * 1024 + (2 * bp + 1) * 32 + c];
            u32 hi, lo; split2h(x0, x1, hi, lo);
            g_GS[((0 * 32 + a) * 32 + c) * 20 + bp] = hi;
            g_GS[((1 * 32 + a) * 32 + c) * 20 + bp] = lo;
        } else {                                 // UOS: o(256) x cp(16)
            int t = task - 24576;
            int o = t >> 4, cp = t & 15;
            float x0 = Uo[o * 32 + 2 * cp];
            float x1 = Uo[o * 32 + 2 * cp + 1];
            u32 hi, lo; split2h(x0, x1, hi, lo);
            g_UOS[(0 * 256 + o) * 20 + cp] = hi;
            g_UOS[(1 * 256 + o) * 20 + cp] = lo;
        }
    }
}

// ================= main =================
__global__ __launch_bounds__(NTH, 2)
void hosvd_mma(const float* __restrict__ X,    // [N][2][256]
               const float* __restrict__ Ub,   // [2][32]
               float* __restrict__ out,        // [N][256]
               int nN)
{
    extern __shared__ __align__(16) char sm[];
    const u32 sb  = s2u(sm);
    const int tid = threadIdx.x;
    const int q   = tid & 3;
    const int cg  = (tid & 31) >> 2;                  // col-group lane (0..7)
    const int r0  = (tid >> 5) * 16 + cg;             // fragment row (m)
    const int base = blockIdx.x * TN;

    if (tid < 64) *(float*)(sm + OFF_UB + tid * 4) = Ub[tid];

    // ================= Phase 1: P = [X_d @ Uw_d^T] =================
    float4 acc1[8];
    #pragma unroll
    for (int fs = 0; fs < 8; fs++) acc1[fs] = make_float4(0.f, 0.f, 0.f, 0.f);

    for (int d = 0; d < 2; d++) {
        for (int ch = 0; ch < 4; ch++) {
            const int c4 = ch * 64;
            __syncthreads();                  // previous MMAs done reading XS/UW
            if (ch == 0) {                    // stage Uw_d via cp.async
                for (int i = tid; i < 2112; i += NTH)
                    cpa16(sb + OFF_UW + i * 16,
                          (const char*)g_UWS + (size_t)d * 33792 + (size_t)i * 16);
                CPA_COMMIT;
            }
            // stage X chunk split: XS[sp][128 n][72 halves]
            #pragma unroll
            for (int g = 0; g < 8; g++) {
                int fid = tid + NTH * g;              // 0..2047
                int row = fid >> 4, f4 = fid & 15;
                int n = base + row;
                float4 v = make_float4(0.f, 0.f, 0.f, 0.f);
                if (n < nN)
                    v = *(const float4*)(X + (size_t)n * 512 + d * 256 + c4 + f4 * 4);
                u32 h0, l0, h1, l1;
                split2h(v.x, v.y, h0, l0);
                split2h(v.z, v.w, h1, l1);
                *(uint2*)(sm + OFF_XS + 0 * 18432 + row * 144 + f4 * 8) = make_uint2(h0, h1);
                *(uint2*)(sm + OFF_XS + 1 * 18432 + row * 144 + f4 * 8) = make_uint2(l0, l1);
            }
            if (ch == 0) CPA_WAIT0;
            __syncthreads();
            #pragma unroll
            for (int ks = 0; ks < 4; ks++) {
                const int kk = ks * 16 + q * 2;
                u32 xh[4], xl[4];
                xh[0] = *(u32*)(sm + OFF_XS + ((r0    ) * 72 + kk    ) * 2);
                xh[1] = *(u32*)(sm + OFF_XS + ((r0 + 8) * 72 + kk    ) * 2);
                xh[2] = *(u32*)(sm + OFF_XS + ((r0    ) * 72 + kk + 8) * 2);
                xh[3] = *(u32*)(sm + OFF_XS + ((r0 + 8) * 72 + kk + 8) * 2);
                xl[0] = *(u32*)(sm + OFF_XS + 18432 + ((r0    ) * 72 + kk    ) * 2);
                xl[1] = *(u32*)(sm + OFF_XS + 18432 + ((r0 + 8) * 72 + kk    ) * 2);
                xl[2] = *(u32*)(sm + OFF_XS + 18432 + ((r0    ) * 72 + kk + 8) * 2);
                xl[3] = *(u32*)(sm + OFF_XS + 18432 + ((r0 + 8) * 72 + kk + 8) * 2);
                #pragma unroll
                for (int nt = 0; nt < 4; nt++) {
                    int ncol = nt * 8 + cg;
                    int bi = (     ncol) * 264 + c4 + kk;   // hi rows 0..31
                    int li = (32 + ncol) * 264 + c4 + kk;   // lo rows 32..63
                    u32 bh0 = *(u32*)(sm + OFF_UW + bi * 2);
                    u32 bh1 = *(u32*)(sm + OFF_UW + (bi + 8) * 2);
                    u32 bl0 = *(u32*)(sm + OFF_UW + li * 2);
                    u32 bl1 = *(u32*)(sm + OFF_UW + (li + 8) * 2);
                    mma16816(acc1[d * 4 + nt], xh[0], xh[1], xh[2], xh[3], bh0, bh1);
                    mma16816(acc1[d * 4 + nt], xl[0], xl[1], xl[2], xl[3], bh0, bh1);
                    mma16816(acc1[d * 4 + nt], xh[0], xh[1], xh[2], xh[3], bl0, bl1);
                }
            }
        }
    }
    __syncthreads();   // phase1 done; UW/XS regions free

    // ---- P epilogue: +bias; d=0 -> P0 fp32; d=1 -> P1S split ----
    {
        float* P0f = (float*)(sm + OFF_P0);
        #pragma unroll
        for (int fs = 0; fs < 8; fs++) {
            int c0 = fs * 8 + q * 2;
            float bx = *(float*)(sm + OFF_UB + c0 * 4);
            float by = *(float*)(sm + OFF_UB + (c0 + 1) * 4);
            float px0 = acc1[fs].x + bx, py0 = acc1[fs].y + by;
            float px1 = acc1[fs].z + bx, py1 = acc1[fs].w + by;
            if (c0 < 32) {
                P0f[r0 * 33 + c0] = px0;       P0f[r0 * 33 + c0 + 1] = py0;
                P0f[(r0 + 8) * 33 + c0] = px1; P0f[(r0 + 8) * 33 + c0 + 1] = py1;
            } else {
                int cc = c0 - 32;
                u32 hi, lo;
                split2h(px0, py0, hi, lo);
                *(u32*)(sm + OFF_P1S + 0 * 10240 + (r0 * 40 + cc) * 2) = hi;
                *(u32*)(sm + OFF_P1S + 1 * 10240 + (r0 * 40 + cc) * 2) = lo;
                split2h(px1, py1, hi, lo);
                *(u32*)(sm + OFF_P1S + 0 * 10240 + ((r0 + 8) * 40 + cc) * 2) = hi;
                *(u32*)(sm + OFF_P1S + 1 * 10240 + ((r0 + 8) * 40 + cc) * 2) = lo;
            }
        }
    }
    __syncthreads();

    // ================= Phase 2: r[n,c] = sum_a p0[n,a] * (p1 @ G[a]^T) =================
    float4 acc2[4];
    #pragma unroll
    for (int nt = 0; nt < 4; nt++) acc2[nt] = make_float4(0.f, 0.f, 0.f, 0.f);
    {
        // preload p1 fragments (regs)
        u32 pH[2][4], pL[2][4];
        #pragma unroll
        for (int ks = 0; ks < 2; ks++) {
            const int kk = ks * 16 + q * 2;
            pH[ks][0] = *(u32*)(sm + OFF_P1S + ((r0    ) * 40 + kk    ) * 2);
            pH[ks][1] = *(u32*)(sm + OFF_P1S + ((r0 + 8) * 40 + kk    ) * 2);
            pH[ks][2] = *(u32*)(sm + OFF_P1S + ((r0    ) * 40 + kk + 8) * 2);
            pH[ks][3] = *(u32*)(sm + OFF_P1S + ((r0 + 8) * 40 + kk + 8) * 2);
            pL[ks][0] = *(u32*)(sm + OFF_P1S + 10240 + ((r0    ) * 40 + kk    ) * 2);
            pL[ks][1] = *(u32*)(sm + OFF_P1S + 10240 + ((r0 + 8) * 40 + kk    ) * 2);
            pL[ks][2] = *(u32*)(sm + OFF_P1S + 10240 + ((r0    ) * 40 + kk + 8) * 2);
            pL[ks][3] = *(u32*)(sm + OFF_P1S + 10240 + ((r0 + 8) * 40 + kk + 8) * 2);
        }
        const float* P0f = (const float*)(sm + OFF_P0);

        // prefetch G chunk 0 (4 a's, hi+lo) via cp.async
        #pragma unroll 1
        for (int i = tid; i < 1280; i += NTH) {
            int sp = (i >= 640) ? 1 : 0;
            int j = i - sp * 640;
            cpa16(sb + OFF_GB + sp * 10240 + j * 16,
                  g_GS + (size_t)sp * 20480 + (size_t)j * 4);
        }
        CPA_COMMIT;

        for (int cch = 0; cch < 8; cch++) {
            CPA_WAIT0;
            __syncthreads();
            if (cch < 7) {
                int pp = (cch + 1) & 1;
                #pragma unroll 1
                for (int i = tid; i < 1280; i += NTH) {
                    int sp = (i >= 640) ? 1 : 0;
                    int j = i - sp * 640;
                    cpa16(sb + OFF_GB + pp * 20480 + sp * 10240 + j * 16,
                          g_GS + (size_t)sp * 20480 + (size_t)(cch + 1) * 2560 + (size_t)j * 4);
                }
                CPA_COMMIT;
            }
            const char* gb = sm + OFF_GB + (cch & 1) * 20480;
            #pragma unroll
            for (int al = 0; al < 4; al++) {
                int a = cch * 4 + al;
                float s0 = P0f[r0 * 33 + a];
                float s1 = P0f[(r0 + 8) * 33 + a];
                #pragma unroll
                for (int nt = 0; nt < 4; nt++) {
                    int cgl = nt * 8 + cg;
                    float4 t4 = make_float4(0.f, 0.f, 0.f, 0.f);
                    #pragma unroll
                    for (int ks = 0; ks < 2; ks++) {
                        const int kk = ks * 16 + q * 2;
                        int gi = ((al * 32 + cgl) * 40 + kk);
                        u32 gh0 = *(u32*)(gb + gi * 2);
                        u32 gh1 = *(u32*)(gb + (gi + 8) * 2);
                        u32 gl0 = *(u32*)(gb + 10240 + gi * 2);
                        u32 gl1 = *(u32*)(gb + 10240 + (gi + 8) * 2);
                        mma16816(t4, pH[ks][0], pH[ks][1], pH[ks][2], pH[ks][3], gh0, gh1);
                        mma16816(t4, pL[ks][0], pL[ks][1], pL[ks][2], pL[ks][3], gh0, gh1);
                        mma16816(t4, pH[ks][0], pH[ks][1], pH[ks][2], pH[ks][3], gl0, gl1);
                    }
                    acc2[nt].x += s0 * t4.x;
                    acc2[nt].y += s0 * t4.y;
                    acc2[nt].z += s1 * t4.z;
                    acc2[nt].w += s1 * t4.w;
                }
            }
        }
    }

    // ---- R epilogue: split -> RS [2][128][40]h (aliases P1S) ----
    #pragma unroll
    for (int nt = 0; nt < 4; nt++) {
        int c0 = nt * 8 + q * 2;
        u32 hi, lo;
        split2h(acc2[nt].x, acc2[nt].y, hi, lo);
        *(u32*)(sm + OFF_RS + 0 * 10240 + (r0 * 40 + c0) * 2) = hi;
        *(u32*)(sm + OFF_RS + 1 * 10240 + (r0 * 40 + c0) * 2) = lo;
        split2h(acc2[nt].z, acc2[nt].w, hi, lo);
        *(u32*)(sm + OFF_RS + 0 * 10240 + ((r0 + 8) * 40 + c0) * 2) = hi;
        *(u32*)(sm + OFF_RS + 1 * 10240 + ((r0 + 8) * 40 + c0) * 2) = lo;
    }
    __syncthreads();   // RS visible; GB region free

    // ---- stage Uo image (aliases GB) ----
    #pragma unroll 1
    for (int i = tid; i < 2560; i += NTH)
        cpa16(sb + OFF_UO + i * 16, (const char*)g_UOS + (size_t)i * 16);
    CPA_COMMIT;

    // preload R fragments while Uo flies
    u32 rH[2][4], rL[2][4];
    #pragma unroll
    for (int ks = 0; ks < 2; ks++) {
        const int kk = ks * 16 + q * 2;
        rH[ks][0] = *(u32*)(sm + OFF_RS + ((r0    ) * 40 + kk    ) * 2);
        rH[ks][1] = *(u32*)(sm + OFF_RS + ((r0 + 8) * 40 + kk    ) * 2);
        rH[ks][2] = *(u32*)(sm + OFF_RS + ((r0    ) * 40 + kk + 8) * 2);
        rH[ks][3] = *(u32*)(sm + OFF_RS + ((r0 + 8) * 40 + kk + 8) * 2);
        rL[ks][0] = *(u32*)(sm + OFF_RS + 10240 + ((r0    ) * 40 + kk    ) * 2);
        rL[ks][1] = *(u32*)(sm + OFF_RS + 10240 + ((r0 + 8) * 40 + kk    ) * 2);
        rL[ks][2] = *(u32*)(sm + OFF_RS + 10240 + ((r0    ) * 40 + kk + 8) * 2);
        rL[ks][3] = *(u32*)(sm + OFF_RS + 10240 + ((r0 + 8) * 40 + kk + 8) * 2);
    }
    CPA_WAIT0;
    __syncthreads();

    // ================= Phase 3: Out = R @ Uo^T, direct STG =================
    const int n0 = base + r0;
    for (int h = 0; h < 2; h++) {
        float4 acc3[16];
        #pragma unroll
        for (int nt = 0; nt < 16; nt++) acc3[nt] = make_float4(0.f, 0.f, 0.f, 0.f);
        #pragma unroll 4
        for (int nt = 0; nt < 16; nt++) {
            int o = h * 128 + nt * 8 + cg;
            #pragma unroll
            for (int ks = 0; ks < 2; ks++) {
                const int kk = ks * 16 + q * 2;
                int ui = o * 40 + kk;
                u32 uh0 = *(u32*)(sm + OFF_UO + ui * 2);
                u32 uh1 = *(u32*)(sm + OFF_UO + (ui + 8) * 2);
                u32 ul0 = *(u32*)(sm + OFF_UO + 20480 + ui * 2);
                u32 ul1 = *(u32*)(sm + OFF_UO + 20480 + (ui + 8) * 2);
                mma16816(acc3[nt], rH[ks][0], rH[ks][1], rH[ks][2], rH[ks][3], uh0, uh1);
                mma16816(acc3[nt], rL[ks][0], rL[ks][1], rL[ks][2], rL[ks][3], uh0, uh1);
                mma16816(acc3[nt], rH[ks][0], rH[ks][1], rH[ks][2], rH[ks][3], ul0, ul1);
            }
        }
        // direct sector-aligned stores: quads cover 32B segments
        #pragma unroll
        for (int nt = 0; nt < 16; nt++) {
            int o0 = h * 128 + nt * 8 + q * 2;
            if (n0 < nN)
                *(float2*)(out + (size_t)n0 * 256 + o0) = make_float2(acc3[nt].x, acc3[nt].y);
            if (n0 + 8 < nN)
                *(float2*)(out + (size_t)(n0 + 8) * 256 + o0) = make_float2(acc3[nt].z, acc3[nt].w);
        }
    }
}

extern "C" void kernel_launch(void* const* d_in, const int* in_sizes, int n_in,
                              void* d_out, int out_size)
{
    const float* X  = (const float*)d_in[0];   // neighbour_states
    const float* Gg = (const float*)d_in[1];   // G
    const float* Uw = (const float*)d_in[2];   // U_w
    const float* Ub = (const float*)d_in[3];   // U_b
    const float* Uo = (const float*)d_in[4];   // U_out
    float* outp = (float*)d_out;

    int nNodes = in_sizes[0] / 512;

    prep_kernel<<<32, 256>>>(Uw, Gg, Uo);

    cudaFuncSetAttribute(hosvd_mma,
                         cudaFuncAttributeMaxDynamicSharedMemorySize, SMEM_TOTAL);
    int grid = (nNodes + TN - 1) / TN;
    hosvd_mma<<<grid, NTH, SMEM_TOTAL>>>(X, Ub, outp, nNodes);
}

// round 6
// speedup vs baseline: 2.8032x; 1.1263x over previous
#include <cuda_runtime.h>
#include <cstdint>

typedef uint32_t u32;

#define TN   128
#define NTH  256

// ---------- global fp16-split weight images (written by prep kernel) ----------
// UWS: [d][sp][32 r][264 halves]   -> u32[16896]
// GS : [sp][32 a][32 c][40 halves] -> u32[40960]
// UOS: [sp][256 o][40 halves]      -> u32[10240]
__device__ __align__(16) u32 g_UWS[16896];
__device__ __align__(16) u32 g_GS[40960];
__device__ __align__(16) u32 g_UOS[10240];

// ---------- smem byte offsets ----------
#define OFF_UB   0            // 256 B (64 floats bias)
#define OFF_P0   256          // fp32 [128][33] = 16896 -> 17152
#define OFF_P1S  17152        // [2][128][40]h = 20480 -> 37632
#define OFF_RS   17152        // alias (phase 3)
#define OFF_SCR  37632
#define OFF_UW   OFF_SCR      // per-d Uw image 33792 -> 71424
#define OFF_GB   OFF_SCR      // G pingpong 2 x 20480 -> 78592
#define OFF_UO   OFF_SCR      // Uo image 40960 -> 78592
#define SMEM_TOTAL 78592

__device__ __forceinline__ u32 s2u(const void* p) {
    u32 a; asm("{.reg .u64 t; cvta.to.shared.u64 t,%1; cvt.u32.u64 %0,t;}" : "=r"(a) : "l"(p));
    return a;
}
__device__ __forceinline__ void cpa16(u32 dst, const void* src) {
    asm volatile("cp.async.ca.shared.global [%0],[%1],16;" :: "r"(dst), "l"(src));
}
#define CPA_COMMIT asm volatile("cp.async.commit_group;" ::: "memory")
#define CPA_WAIT0  asm volatile("cp.async.wait_group 0;" ::: "memory")

__device__ __forceinline__ void ldmx4(u32& r0, u32& r1, u32& r2, u32& r3, u32 addr) {
    asm volatile("ldmatrix.sync.aligned.m8n8.x4.shared.b16 {%0,%1,%2,%3},[%4];"
                 : "=r"(r0), "=r"(r1), "=r"(r2), "=r"(r3) : "r"(addr));
}

// pack two f32 -> f16x2 (flo -> bits[15:0])
__device__ __forceinline__ u32 pkh(float flo, float fhi) {
    u32 r; asm("cvt.rn.f16x2.f32 %0,%1,%2;" : "=r"(r) : "f"(fhi), "f"(flo)); return r;
}
__device__ __forceinline__ void uph(u32 p, float& flo, float& fhi) {
    asm("{.reg .f16 a,b; mov.b32 {a,b},%2; cvt.f32.f16 %0,a; cvt.f32.f16 %1,b;}"
        : "=f"(flo), "=f"(fhi) : "r"(p));
}
__device__ __forceinline__ void split2h(float x, float y, u32& hi, u32& lo) {
    hi = pkh(x, y);
    float hx, hy; uph(hi, hx, hy);
    lo = pkh(x - hx, y - hy);
}
__device__ __forceinline__ void mma16816(float4& d, u32 a0, u32 a1, u32 a2, u32 a3,
                                         u32 b0, u32 b1) {
    asm volatile(
        "mma.sync.aligned.m16n8k16.row.col.f32.f16.f16.f32 "
        "{%0,%1,%2,%3},{%4,%5,%6,%7},{%8,%9},{%0,%1,%2,%3};"
        : "+f"(d.x), "+f"(d.y), "+f"(d.z), "+f"(d.w)
        : "r"(a0), "r"(a1), "r"(a2), "r"(a3), "r"(b0), "r"(b1));
}

// ================= prep: split weights to fp16 hi/lo global images =================
__global__ void prep_kernel(const float* __restrict__ Uw,
                            const float* __restrict__ Gg,
                            const float* __restrict__ Uo)
{
    for (int task = blockIdx.x * blockDim.x + threadIdx.x; task < 28672;
         task += gridDim.x * blockDim.x) {
        if (task < 8192) {                       // UWS: d(2) x r(32) x ip(128)
            int d = task >> 12, r = (task >> 7) & 31, ip = task & 127;
            float x0 = Uw[d * 8192 + r * 256 + 2 * ip];
            float x1 = Uw[d * 8192 + r * 256 + 2 * ip + 1];
            u32 hi, lo; split2h(x0, x1, hi, lo);
            g_UWS[((d * 2 + 0) * 32 + r) * 132 + ip] = hi;
            g_UWS[((d * 2 + 1) * 32 + r) * 132 + ip] = lo;
        } else if (task < 24576) {               // GS: a(32) x c(32) x bp(16)
            int t = task - 8192;
            int a = t >> 9, c = (t >> 4) & 31, bp = t & 15;
            float x0 = Gg[a * 1024 + (2 * bp) * 32 + c];
            float x1 = Gg[a * 1024 + (2 * bp + 1) * 32 + c];
            u32 hi, lo; split2h(x0, x1, hi, lo);
            g_GS[((0 * 32 + a) * 32 + c) * 20 + bp] = hi;
            g_GS[((1 * 32 + a) * 32 + c) * 20 + bp] = lo;
        } else {                                 // UOS: o(256) x cp(16)
            int t = task - 24576;
            int o = t >> 4, cp = t & 15;
            float x0 = Uo[o * 32 + 2 * cp];
            float x1 = Uo[o * 32 + 2 * cp + 1];
            u32 hi, lo; split2h(x0, x1, hi, lo);
            g_UOS[(0 * 256 + o) * 20 + cp] = hi;
            g_UOS[(1 * 256 + o) * 20 + cp] = lo;
        }
    }
}

// ================= main =================
__global__ __launch_bounds__(NTH, 2)
void hosvd_mma(const float* __restrict__ X,    // [N][2][256]
               const float* __restrict__ Ub,   // [2][32]
               float* __restrict__ out,        // [N][256]
               int nN)
{
    extern __shared__ __align__(16) char sm[];
    const u32 sb   = s2u(sm);
    const int tid  = threadIdx.x;
    const int lane = tid & 31;
    const int q    = lane & 3;
    const int cg   = lane >> 2;                       // col-group (0..7)
    const int r0   = (tid >> 5) * 16 + cg;            // fragment row
    const int base = blockIdx.x * TN;
    const bool ok0 = (base + r0) < nN;
    const bool ok1 = (base + r0 + 8) < nN;

    // per-thread ldmatrix base offset within an image region:
    // row (lane&7) * stride + matrix (lane>>3) * 16 bytes
    const int lm8 = lane & 7, lmm = lane >> 3;
    const u32 lmW = (u32)(lm8 * 528 + lmm * 16);      // stride 264 halves
    const u32 lm40 = (u32)(lm8 * 80 + lmm * 16);      // stride 40 halves

    if (tid < 64) *(float*)(sm + OFF_UB + tid * 4) = Ub[tid];

    // ================= Phase 1: P = [X_d @ Uw_d^T] =================
    float4 acc1[8];
    #pragma unroll
    for (int fs = 0; fs < 8; fs++) acc1[fs] = make_float4(0.f, 0.f, 0.f, 0.f);

    for (int d = 0; d < 2; d++) {
        __syncthreads();                      // previous users of region done
        for (int i = tid; i < 2112; i += NTH)
            cpa16(sb + OFF_UW + i * 16,
                  (const char*)g_UWS + (size_t)d * 33792 + (size_t)i * 16);
        CPA_COMMIT;

        for (int ch = 0; ch < 4; ch++) {
            const int c4 = ch * 64;
            // A fragments direct from global, split in registers
            u32 xh[4][4], xl[4][4];
            const float* xb = X + (size_t)base * 512 + d * 256 + c4;
            #pragma unroll
            for (int ks = 0; ks < 4; ks++) {
                const int kk = ks * 16 + q * 2;
                float2 v00 = ok0 ? *(const float2*)(xb + (size_t)r0 * 512 + kk)
                                 : make_float2(0.f, 0.f);
                float2 v10 = ok1 ? *(const float2*)(xb + (size_t)(r0 + 8) * 512 + kk)
                                 : make_float2(0.f, 0.f);
                float2 v01 = ok0 ? *(const float2*)(xb + (size_t)r0 * 512 + kk + 8)
                                 : make_float2(0.f, 0.f);
                float2 v11 = ok1 ? *(const float2*)(xb + (size_t)(r0 + 8) * 512 + kk + 8)
                                 : make_float2(0.f, 0.f);
                split2h(v00.x, v00.y, xh[ks][0], xl[ks][0]);
                split2h(v10.x, v10.y, xh[ks][1], xl[ks][1]);
                split2h(v01.x, v01.y, xh[ks][2], xl[ks][2]);
                split2h(v11.x, v11.y, xh[ks][3], xl[ks][3]);
            }
            if (ch == 0) { CPA_WAIT0; __syncthreads(); }

            const u32 wb = sb + OFF_UW + lmW + (u32)(c4 * 2);
            #pragma unroll
            for (int nt = 0; nt < 4; nt++) {
                u32 bh[8], bl[8];
                u32 a0 = wb + (u32)(nt * 4224);
                ldmx4(bh[0], bh[1], bh[2], bh[3], a0);
                ldmx4(bh[4], bh[5], bh[6], bh[7], a0 + 64);
                ldmx4(bl[0], bl[1], bl[2], bl[3], a0 + 16896);
                ldmx4(bl[4], bl[5], bl[6], bl[7], a0 + 16896 + 64);
                #pragma unroll
                for (int ks = 0; ks < 4; ks++) {
                    mma16816(acc1[d * 4 + nt], xh[ks][0], xh[ks][1], xh[ks][2], xh[ks][3],
                             bh[ks * 2], bh[ks * 2 + 1]);
                    mma16816(acc1[d * 4 + nt], xl[ks][0], xl[ks][1], xl[ks][2], xl[ks][3],
                             bh[ks * 2], bh[ks * 2 + 1]);
                    mma16816(acc1[d * 4 + nt], xh[ks][0], xh[ks][1], xh[ks][2], xh[ks][3],
                             bl[ks * 2], bl[ks * 2 + 1]);
                }
            }
        }
    }
    __syncthreads();   // phase1 done; UW region free

    // ---- P epilogue: +bias; d=0 -> P0 fp32; d=1 -> P1S split ----
    {
        float* P0f = (float*)(sm + OFF_P0);
        #pragma unroll
        for (int fs = 0; fs < 8; fs++) {
            int c0 = fs * 8 + q * 2;
            float bx = *(float*)(sm + OFF_UB + c0 * 4);
            float by = *(float*)(sm + OFF_UB + (c0 + 1) * 4);
            float px0 = acc1[fs].x + bx, py0 = acc1[fs].y + by;
            float px1 = acc1[fs].z + bx, py1 = acc1[fs].w + by;
            if (c0 < 32) {
                P0f[r0 * 33 + c0] = px0;       P0f[r0 * 33 + c0 + 1] = py0;
                P0f[(r0 + 8) * 33 + c0] = px1; P0f[(r0 + 8) * 33 + c0 + 1] = py1;
            } else {
                int cc = c0 - 32;
                u32 hi, lo;
                split2h(px0, py0, hi, lo);
                *(u32*)(sm + OFF_P1S + 0 * 10240 + (r0 * 40 + cc) * 2) = hi;
                *(u32*)(sm + OFF_P1S + 1 * 10240 + (r0 * 40 + cc) * 2) = lo;
                split2h(px1, py1, hi, lo);
                *(u32*)(sm + OFF_P1S + 0 * 10240 + ((r0 + 8) * 40 + cc) * 2) = hi;
                *(u32*)(sm + OFF_P1S + 1 * 10240 + ((r0 + 8) * 40 + cc) * 2) = lo;
            }
        }
    }
    __syncthreads();

    // ================= Phase 2: r[n,c] = sum_a p0[n,a] * (p1 @ G[a]^T) =================
    float4 acc2[4];
    #pragma unroll
    for (int nt = 0; nt < 4; nt++) acc2[nt] = make_float4(0.f, 0.f, 0.f, 0.f);
    {
        u32 pH[2][4], pL[2][4];
        #pragma unroll
        for (int ks = 0; ks < 2; ks++) {
            const int kk = ks * 16 + q * 2;
            pH[ks][0] = *(u32*)(sm + OFF_P1S + ((r0    ) * 40 + kk    ) * 2);
            pH[ks][1] = *(u32*)(sm + OFF_P1S + ((r0 + 8) * 40 + kk    ) * 2);
            pH[ks][2] = *(u32*)(sm + OFF_P1S + ((r0    ) * 40 + kk + 8) * 2);
            pH[ks][3] = *(u32*)(sm + OFF_P1S + ((r0 + 8) * 40 + kk + 8) * 2);
            pL[ks][0] = *(u32*)(sm + OFF_P1S + 10240 + ((r0    ) * 40 + kk    ) * 2);
            pL[ks][1] = *(u32*)(sm + OFF_P1S + 10240 + ((r0 + 8) * 40 + kk    ) * 2);
            pL[ks][2] = *(u32*)(sm + OFF_P1S + 10240 + ((r0    ) * 40 + kk + 8) * 2);
            pL[ks][3] = *(u32*)(sm + OFF_P1S + 10240 + ((r0 + 8) * 40 + kk + 8) * 2);
        }
        const float* P0f = (const float*)(sm + OFF_P0);

        // prefetch G chunk 0 (4 a's, hi+lo)
        #pragma unroll 1
        for (int i = tid; i < 1280; i += NTH) {
            int sp = (i >= 640) ? 1 : 0;
            int j = i - sp * 640;
            cpa16(sb + OFF_GB + sp * 10240 + j * 16,
                  g_GS + (size_t)sp * 20480 + (size_t)j * 4);
        }
        CPA_COMMIT;

        for (int cch = 0; cch < 8; cch++) {
            CPA_WAIT0;
            __syncthreads();
            if (cch < 7) {
                int pp = (cch + 1) & 1;
                #pragma unroll 1
                for (int i = tid; i < 1280; i += NTH) {
                    int sp = (i >= 640) ? 1 : 0;
                    int j = i - sp * 640;
                    cpa16(sb + OFF_GB + pp * 20480 + sp * 10240 + j * 16,
                          g_GS + (size_t)sp * 20480 + (size_t)(cch + 1) * 2560 + (size_t)j * 4);
                }
                CPA_COMMIT;
            }
            const u32 gb = sb + OFF_GB + (u32)((cch & 1) * 20480) + lm40;
            #pragma unroll
            for (int al = 0; al < 4; al++) {
                int a = cch * 4 + al;
                float s0 = P0f[r0 * 33 + a];
                float s1 = P0f[(r0 + 8) * 33 + a];
                #pragma unroll
                for (int nt = 0; nt < 4; nt++) {
                    u32 gh[4], gl[4];
                    u32 ga = gb + (u32)((al * 32 + nt * 8) * 80);
                    ldmx4(gh[0], gh[1], gh[2], gh[3], ga);
                    ldmx4(gl[0], gl[1], gl[2], gl[3], ga + 10240);
                    float4 t4 = make_float4(0.f, 0.f, 0.f, 0.f);
                    mma16816(t4, pH[0][0], pH[0][1], pH[0][2], pH[0][3], gh[0], gh[1]);
                    mma16816(t4, pH[1][0], pH[1][1], pH[1][2], pH[1][3], gh[2], gh[3]);
                    mma16816(t4, pL[0][0], pL[0][1], pL[0][2], pL[0][3], gh[0], gh[1]);
                    mma16816(t4, pL[1][0], pL[1][1], pL[1][2], pL[1][3], gh[2], gh[3]);
                    mma16816(t4, pH[0][0], pH[0][1], pH[0][2], pH[0][3], gl[0], gl[1]);
                    mma16816(t4, pH[1][0], pH[1][1], pH[1][2], pH[1][3], gl[2], gl[3]);
                    acc2[nt].x += s0 * t4.x;
                    acc2[nt].y += s0 * t4.y;
                    acc2[nt].z += s1 * t4.z;
                    acc2[nt].w += s1 * t4.w;
                }
            }
        }
    }

    // ---- R epilogue: split -> RS [2][128][40]h (aliases P1S) ----
    #pragma unroll
    for (int nt = 0; nt < 4; nt++) {
        int c0 = nt * 8 + q * 2;
        u32 hi, lo;
        split2h(acc2[nt].x, acc2[nt].y, hi, lo);
        *(u32*)(sm + OFF_RS + 0 * 10240 + (r0 * 40 + c0) * 2) = hi;
        *(u32*)(sm + OFF_RS + 1 * 10240 + (r0 * 40 + c0) * 2) = lo;
        split2h(acc2[nt].z, acc2[nt].w, hi, lo);
        *(u32*)(sm + OFF_RS + 0 * 10240 + ((r0 + 8) * 40 + c0) * 2) = hi;
        *(u32*)(sm + OFF_RS + 1 * 10240 + ((r0 + 8) * 40 + c0) * 2) = lo;
    }
    __syncthreads();   // RS visible; GB region free

    // ---- stage Uo image (aliases GB) ----
    #pragma unroll 1
    for (int i = tid; i < 2560; i += NTH)
        cpa16(sb + OFF_UO + i * 16, (const char*)g_UOS + (size_t)i * 16);
    CPA_COMMIT;

    // preload R fragments while Uo flies
    u32 rH[2][4], rL[2][4];
    #pragma unroll
    for (int ks = 0; ks < 2; ks++) {
        const int kk = ks * 16 + q * 2;
        rH[ks][0] = *(u32*)(sm + OFF_RS + ((r0    ) * 40 + kk    ) * 2);
        rH[ks][1] = *(u32*)(sm + OFF_RS + ((r0 + 8) * 40 + kk    ) * 2);
        rH[ks][2] = *(u32*)(sm + OFF_RS + ((r0    ) * 40 + kk + 8) * 2);
        rH[ks][3] = *(u32*)(sm + OFF_RS + ((r0 + 8) * 40 + kk + 8) * 2);
        rL[ks][0] = *(u32*)(sm + OFF_RS + 10240 + ((r0    ) * 40 + kk    ) * 2);
        rL[ks][1] = *(u32*)(sm + OFF_RS + 10240 + ((r0 + 8) * 40 + kk    ) * 2);
        rL[ks][2] = *(u32*)(sm + OFF_RS + 10240 + ((r0    ) * 40 + kk + 8) * 2);
        rL[ks][3] = *(u32*)(sm + OFF_RS + 10240 + ((r0 + 8) * 40 + kk + 8) * 2);
    }
    CPA_WAIT0;
    __syncthreads();

    // ================= Phase 3: Out = R @ Uo^T, direct STG =================
    const int n0 = base + r0;
    const u32 ub3 = sb + OFF_UO + lm40;
    for (int h = 0; h < 2; h++) {
        float4 acc3[16];
        #pragma unroll
        for (int nt = 0; nt < 16; nt++) acc3[nt] = make_float4(0.f, 0.f, 0.f, 0.f);
        #pragma unroll 4
        for (int nt = 0; nt < 16; nt++) {
            u32 uh[4], ul[4];
            u32 ua = ub3 + (u32)((h * 128 + nt * 8) * 80);
            ldmx4(uh[0], uh[1], uh[2], uh[3], ua);
            ldmx4(ul[0], ul[1], ul[2], ul[3], ua + 20480);
            mma16816(acc3[nt], rH[0][0], rH[0][1], rH[0][2], rH[0][3], uh[0], uh[1]);
            mma16816(acc3[nt], rH[1][0], rH[1][1], rH[1][2], rH[1][3], uh[2], uh[3]);
            mma16816(acc3[nt], rL[0][0], rL[0][1], rL[0][2], rL[0][3], uh[0], uh[1]);
            mma16816(acc3[nt], rL[1][0], rL[1][1], rL[1][2], rL[1][3], uh[2], uh[3]);
            mma16816(acc3[nt], rH[0][0], rH[0][1], rH[0][2], rH[0][3], ul[0], ul[1]);
            mma16816(acc3[nt], rH[1][0], rH[1][1], rH[1][2], rH[1][3], ul[2], ul[3]);
        }
        // direct sector-aligned stores: quads cover 32B segments
        #pragma unroll
        for (int nt = 0; nt < 16; nt++) {
            int o0 = h * 128 + nt * 8 + q * 2;
            if (ok0)
                *(float2*)(out + (size_t)n0 * 256 + o0) = make_float2(acc3[nt].x, acc3[nt].y);
            if (ok1)
                *(float2*)(out + (size_t)(n0 + 8) * 256 + o0) = make_float2(acc3[nt].z, acc3[nt].w);
        }
    }
}

extern "C" void kernel_launch(void* const* d_in, const int* in_sizes, int n_in,
                              void* d_out, int out_size)
{
    const float* X  = (const float*)d_in[0];   // neighbour_states
    const float* Gg = (const float*)d_in[1];   // G
    const float* Uw = (const float*)d_in[2];   // U_w
    const float* Ub = (const float*)d_in[3];   // U_b
    const float* Uo = (const float*)d_in[4];   // U_out
    float* outp = (float*)d_out;

    int nNodes = in_sizes[0] / 512;

    prep_kernel<<<32, 256>>>(Uw, Gg, Uo);

    cudaFuncSetAttribute(hosvd_mma,
                         cudaFuncAttributeMaxDynamicSharedMemorySize, SMEM_TOTAL);
    int grid = (nNodes + TN - 1) / TN;
    hosvd_mma<<<grid, NTH, SMEM_TOTAL>>>(X, Ub, outp, nNodes);
}

// round 7
// speedup vs baseline: 3.3001x; 1.1772x over previous
#include <cuda_runtime.h>
#include <cstdint>

typedef uint32_t u32;

#define TN   128
#define NTH  128

// ---------- global fp16-split weight images (written by prep kernel) ----------
// UWS: [d][sp][32 r][264 halves]   -> u32[16896]
// GS : [sp][32 a][32 c][40 halves] -> u32[40960]
// UOS: [sp][256 o][40 halves]      -> u32[10240]
__device__ __align__(16) u32 g_UWS[16896];
__device__ __align__(16) u32 g_GS[40960];
__device__ __align__(16) u32 g_UOS[10240];

// ---------- smem byte offsets ----------
#define OFF_UB   0            // 256 B bias
#define OFF_P0   256          // fp32 [128][33] = 16896 -> 17152
#define OFF_P1S  17152        // [2][128][40]h = 20480 -> 37632 (sp stride 10240)
#define OFF_RS   17152        // alias (phase 3)
#define OFF_SCR  37632
#define OFF_UW   OFF_SCR      // per-d Uw image 33792 -> 71424
#define OFF_GB   OFF_SCR      // G pingpong 2 x 10240 = 20480
#define OFF_UO   OFF_SCR      // Uo half image 20480
#define SMEM_TOTAL 71424      // x3 CTAs = 214272

__device__ __forceinline__ u32 s2u(const void* p) {
    u32 a; asm("{.reg .u64 t; cvta.to.shared.u64 t,%1; cvt.u32.u64 %0,t;}" : "=r"(a) : "l"(p));
    return a;
}
__device__ __forceinline__ void cpa16(u32 dst, const void* src) {
    asm volatile("cp.async.ca.shared.global [%0],[%1],16;" :: "r"(dst), "l"(src));
}
#define CPA_COMMIT asm volatile("cp.async.commit_group;" ::: "memory")
#define CPA_WAIT0  asm volatile("cp.async.wait_group 0;" ::: "memory")

__device__ __forceinline__ void ldmx4(u32& r0, u32& r1, u32& r2, u32& r3, u32 addr) {
    asm volatile("ldmatrix.sync.aligned.m8n8.x4.shared.b16 {%0,%1,%2,%3},[%4];"
                 : "=r"(r0), "=r"(r1), "=r"(r2), "=r"(r3) : "r"(addr));
}

// pack two f32 -> f16x2 (flo -> bits[15:0])
__device__ __forceinline__ u32 pkh(float flo, float fhi) {
    u32 r; asm("cvt.rn.f16x2.f32 %0,%1,%2;" : "=r"(r) : "f"(fhi), "f"(flo)); return r;
}
__device__ __forceinline__ void uph(u32 p, float& flo, float& fhi) {
    asm("{.reg .f16 a,b; mov.b32 {a,b},%2; cvt.f32.f16 %0,a; cvt.f32.f16 %1,b;}"
        : "=f"(flo), "=f"(fhi) : "r"(p));
}
__device__ __forceinline__ void split2h(float x, float y, u32& hi, u32& lo) {
    hi = pkh(x, y);
    float hx, hy; uph(hi, hx, hy);
    lo = pkh(x - hx, y - hy);
}
__device__ __forceinline__ void mma16816(float4& d, u32 a0, u32 a1, u32 a2, u32 a3,
                                         u32 b0, u32 b1) {
    asm volatile(
        "mma.sync.aligned.m16n8k16.row.col.f32.f16.f16.f32 "
        "{%0,%1,%2,%3},{%4,%5,%6,%7},{%8,%9},{%0,%1,%2,%3};"
        : "+f"(d.x), "+f"(d.y), "+f"(d.z), "+f"(d.w)
        : "r"(a0), "r"(a1), "r"(a2), "r"(a3), "r"(b0), "r"(b1));
}

// ================= prep: split weights to fp16 hi/lo global images =================
__global__ void prep_kernel(const float* __restrict__ Uw,
                            const float* __restrict__ Gg,
                            const float* __restrict__ Uo)
{
    for (int task = blockIdx.x * blockDim.x + threadIdx.x; task < 28672;
         task += gridDim.x * blockDim.x) {
        if (task < 8192) {                       // UWS: d(2) x r(32) x ip(128)
            int d = task >> 12, r = (task >> 7) & 31, ip = task & 127;
            float x0 = Uw[d * 8192 + r * 256 + 2 * ip];
            float x1 = Uw[d * 8192 + r * 256 + 2 * ip + 1];
            u32 hi, lo; split2h(x0, x1, hi, lo);
            g_UWS[((d * 2 + 0) * 32 + r) * 132 + ip] = hi;
            g_UWS[((d * 2 + 1) * 32 + r) * 132 + ip] = lo;
        } else if (task < 24576) {               // GS: a(32) x c(32) x bp(16)
            int t = task - 8192;
            int a = t >> 9, c = (t >> 4) & 31, bp = t & 15;
            float x0 = Gg[a * 1024 + (2 * bp) * 32 + c];
            float x1 = Gg[a * 1024 + (2 * bp + 1) * 32 + c];
            u32 hi, lo; split2h(x0, x1, hi, lo);
            g_GS[((0 * 32 + a) * 32 + c) * 20 + bp] = hi;
            g_GS[((1 * 32 + a) * 32 + c) * 20 + bp] = lo;
        } else {                                 // UOS: o(256) x cp(16)
            int t = task - 24576;
            int o = t >> 4, cp = t & 15;
            float x0 = Uo[o * 32 + 2 * cp];
            float x1 = Uo[o * 32 + 2 * cp + 1];
            u32 hi, lo; split2h(x0, x1, hi, lo);
            g_UOS[(0 * 256 + o) * 20 + cp] = hi;
            g_UOS[(1 * 256 + o) * 20 + cp] = lo;
        }
    }
}

// ================= main: 4 warps, m32 per warp (two m16 blocks) =================
__global__ __launch_bounds__(NTH, 3)
void hosvd_mma(const float* __restrict__ X,    // [N][2][256]
               const float* __restrict__ Ub,   // [2][32]
               float* __restrict__ out,        // [N][256]
               int nN)
{
    extern __shared__ __align__(16) char sm[];
    const u32 sb   = s2u(sm);
    const int tid  = threadIdx.x;
    const int lane = tid & 31;
    const int q    = lane & 3;
    const int cg   = lane >> 2;
    const int rw   = (tid >> 5) * 32;                 // warp row base (0/32/64/96)
    const int base = blockIdx.x * TN;

    const int lm8 = lane & 7, lmm = lane >> 3;
    const u32 lmW  = (u32)(lm8 * 528 + lmm * 16);     // Uw image, 264h rows
    const u32 lm40 = (u32)(lm8 * 80 + lmm * 16);      // 40h rows (G/Uo)

    int  rA[2], rB[2];
    bool okA[2], okB[2];
    #pragma unroll
    for (int rb = 0; rb < 2; rb++) {
        rA[rb] = rw + rb * 16 + cg;
        rB[rb] = rA[rb] + 8;
        okA[rb] = (base + rA[rb]) < nN;
        okB[rb] = (base + rB[rb]) < nN;
    }

    if (tid < 64) *(float*)(sm + OFF_UB + tid * 4) = Ub[tid];

    // ================= Phase 1: P = [X_d @ Uw_d^T] =================
    for (int d = 0; d < 2; d++) {
        __syncthreads();                      // previous users of UW region done
        for (int i = tid; i < 2112; i += NTH)
            cpa16(sb + OFF_UW + i * 16,
                  (const char*)g_UWS + (size_t)d * 33792 + (size_t)i * 16);
        CPA_COMMIT;

        float4 acc[2][4];
        #pragma unroll
        for (int rb = 0; rb < 2; rb++)
            #pragma unroll
            for (int nt = 0; nt < 4; nt++) acc[rb][nt] = make_float4(0.f, 0.f, 0.f, 0.f);

        const float* xb = X + (size_t)base * 512 + d * 256;

        for (int ch = 0; ch < 4; ch++) {
            const int c4 = ch * 64;
            #pragma unroll
            for (int ksh = 0; ksh < 2; ksh++) {
                // A fragments direct from global, split in regs: [rb][ks2][4]
                u32 xh[2][2][4], xl[2][2][4];
                #pragma unroll
                for (int rb = 0; rb < 2; rb++)
                    #pragma unroll
                    for (int ks2 = 0; ks2 < 2; ks2++) {
                        const int kk = c4 + ksh * 32 + ks2 * 16 + q * 2;
                        float2 v00 = okA[rb] ? *(const float2*)(xb + (size_t)rA[rb] * 512 + kk)
                                             : make_float2(0.f, 0.f);
                        float2 v10 = okB[rb] ? *(const float2*)(xb + (size_t)rB[rb] * 512 + kk)
                                             : make_float2(0.f, 0.f);
                        float2 v01 = okA[rb] ? *(const float2*)(xb + (size_t)rA[rb] * 512 + kk + 8)
                                             : make_float2(0.f, 0.f);
                        float2 v11 = okB[rb] ? *(const float2*)(xb + (size_t)rB[rb] * 512 + kk + 8)
                                             : make_float2(0.f, 0.f);
                        split2h(v00.x, v00.y, xh[rb][ks2][0], xl[rb][ks2][0]);
                        split2h(v10.x, v10.y, xh[rb][ks2][1], xl[rb][ks2][1]);
                        split2h(v01.x, v01.y, xh[rb][ks2][2], xl[rb][ks2][2]);
                        split2h(v11.x, v11.y, xh[rb][ks2][3], xl[rb][ks2][3]);
                    }
                if (ch == 0 && ksh == 0) { CPA_WAIT0; __syncthreads(); }

                const u32 wb = sb + OFF_UW + lmW + (u32)((c4 + ksh * 32) * 2);
                #pragma unroll
                for (int nt = 0; nt < 4; nt++) {
                    u32 bh[4], bl[4];
                    u32 a0 = wb + (u32)(nt * 4224);
                    ldmx4(bh[0], bh[1], bh[2], bh[3], a0);
                    ldmx4(bl[0], bl[1], bl[2], bl[3], a0 + 16896);
                    #pragma unroll
                    for (int rb = 0; rb < 2; rb++)
                        #pragma unroll
                        for (int ks2 = 0; ks2 < 2; ks2++) {
                            mma16816(acc[rb][nt],
                                     xh[rb][ks2][0], xh[rb][ks2][1], xh[rb][ks2][2], xh[rb][ks2][3],
                                     bh[ks2 * 2], bh[ks2 * 2 + 1]);
                            mma16816(acc[rb][nt],
                                     xl[rb][ks2][0], xl[rb][ks2][1], xl[rb][ks2][2], xl[rb][ks2][3],
                                     bh[ks2 * 2], bh[ks2 * 2 + 1]);
                            mma16816(acc[rb][nt],
                                     xh[rb][ks2][0], xh[rb][ks2][1], xh[rb][ks2][2], xh[rb][ks2][3],
                                     bl[ks2 * 2], bl[ks2 * 2 + 1]);
                        }
                }
            }
        }

        // epilogue for this d: +bias; d=0 -> P0 fp32; d=1 -> P1S split
        float* P0f = (float*)(sm + OFF_P0);
        #pragma unroll
        for (int rb = 0; rb < 2; rb++)
            #pragma unroll
            for (int nt = 0; nt < 4; nt++) {
                int c0 = nt * 8 + q * 2;
                float bx = *(float*)(sm + OFF_UB + (d * 32 + c0) * 4);
                float by = *(float*)(sm + OFF_UB + (d * 32 + c0 + 1) * 4);
                float px0 = acc[rb][nt].x + bx, py0 = acc[rb][nt].y + by;
                float px1 = acc[rb][nt].z + bx, py1 = acc[rb][nt].w + by;
                if (d == 0) {
                    P0f[rA[rb] * 33 + c0] = px0;  P0f[rA[rb] * 33 + c0 + 1] = py0;
                    P0f[rB[rb] * 33 + c0] = px1;  P0f[rB[rb] * 33 + c0 + 1] = py1;
                } else {
                    u32 hi, lo;
                    split2h(px0, py0, hi, lo);
                    *(u32*)(sm + OFF_P1S + (rA[rb] * 40 + c0) * 2) = hi;
                    *(u32*)(sm + OFF_P1S + 10240 + (rA[rb] * 40 + c0) * 2) = lo;
                    split2h(px1, py1, hi, lo);
                    *(u32*)(sm + OFF_P1S + (rB[rb] * 40 + c0) * 2) = hi;
                    *(u32*)(sm + OFF_P1S + 10240 + (rB[rb] * 40 + c0) * 2) = lo;
                }
            }
    }
    __syncthreads();   // P visible; UW region free

    // ================= Phase 2: r[n,c] = sum_a p0[n,a] * (p1 @ G[a]^T) =================
    float4 acc2[2][4];
    #pragma unroll
    for (int rb = 0; rb < 2; rb++)
        #pragma unroll
        for (int nt = 0; nt < 4; nt++) acc2[rb][nt] = make_float4(0.f, 0.f, 0.f, 0.f);
    {
        u32 pH[2][2][4], pL[2][2][4];          // [rb][ks][frag]
        #pragma unroll
        for (int rb = 0; rb < 2; rb++)
            #pragma unroll
            for (int ks = 0; ks < 2; ks++) {
                const int kk = ks * 16 + q * 2;
                pH[rb][ks][0] = *(u32*)(sm + OFF_P1S + (rA[rb] * 40 + kk) * 2);
                pH[rb][ks][1] = *(u32*)(sm + OFF_P1S + (rB[rb] * 40 + kk) * 2);
                pH[rb][ks][2] = *(u32*)(sm + OFF_P1S + (rA[rb] * 40 + kk + 8) * 2);
                pH[rb][ks][3] = *(u32*)(sm + OFF_P1S + (rB[rb] * 40 + kk + 8) * 2);
                pL[rb][ks][0] = *(u32*)(sm + OFF_P1S + 10240 + (rA[rb] * 40 + kk) * 2);
                pL[rb][ks][1] = *(u32*)(sm + OFF_P1S + 10240 + (rB[rb] * 40 + kk) * 2);
                pL[rb][ks][2] = *(u32*)(sm + OFF_P1S + 10240 + (rA[rb] * 40 + kk + 8) * 2);
                pL[rb][ks][3] = *(u32*)(sm + OFF_P1S + 10240 + (rB[rb] * 40 + kk + 8) * 2);
            }
        const float* P0f = (const float*)(sm + OFF_P0);

        // prefetch G chunk 0 (2 a's, hi+lo): 640 x 16B
        #pragma unroll 1
        for (int i = tid; i < 640; i += NTH) {
            int sp = (i >= 320) ? 1 : 0;
            int j = i - sp * 320;
            cpa16(sb + OFF_GB + sp * 5120 + j * 16,
                  g_GS + (size_t)sp * 20480 + (size_t)j * 4);
        }
        CPA_COMMIT;

        for (int cc = 0; cc < 16; cc++) {
            CPA_WAIT0;
            __syncthreads();
            if (cc < 15) {
                int pp = (cc + 1) & 1;
                #pragma unroll 1
                for (int i = tid; i < 640; i += NTH) {
                    int sp = (i >= 320) ? 1 : 0;
                    int j = i - sp * 320;
                    cpa16(sb + OFF_GB + pp * 10240 + sp * 5120 + j * 16,
                          g_GS + (size_t)sp * 20480 + (size_t)(cc + 1) * 1280 + (size_t)j * 4);
                }
                CPA_COMMIT;
            }
            const u32 gb = sb + OFF_GB + (u32)((cc & 1) * 10240) + lm40;
            #pragma unroll
            for (int al = 0; al < 2; al++) {
                const int a = cc * 2 + al;
                float s0[2], s1[2];
                #pragma unroll
                for (int rb = 0; rb < 2; rb++) {
                    s0[rb] = P0f[rA[rb] * 33 + a];
                    s1[rb] = P0f[rB[rb] * 33 + a];
                }
                #pragma unroll
                for (int nt = 0; nt < 4; nt++) {
                    u32 gh[4], gl[4];
                    u32 ga = gb + (u32)(al * 2560 + nt * 640);
                    ldmx4(gh[0], gh[1], gh[2], gh[3], ga);
                    ldmx4(gl[0], gl[1], gl[2], gl[3], ga + 5120);
                    #pragma unroll
                    for (int rb = 0; rb < 2; rb++) {
                        float4 t4 = make_float4(0.f, 0.f, 0.f, 0.f);
                        mma16816(t4, pH[rb][0][0], pH[rb][0][1], pH[rb][0][2], pH[rb][0][3], gh[0], gh[1]);
                        mma16816(t4, pH[rb][1][0], pH[rb][1][1], pH[rb][1][2], pH[rb][1][3], gh[2], gh[3]);
                        mma16816(t4, pL[rb][0][0], pL[rb][0][1], pL[rb][0][2], pL[rb][0][3], gh[0], gh[1]);
                        mma16816(t4, pL[rb][1][0], pL[rb][1][1], pL[rb][1][2], pL[rb][1][3], gh[2], gh[3]);
                        mma16816(t4, pH[rb][0][0], pH[rb][0][1], pH[rb][0][2], pH[rb][0][3], gl[0], gl[1]);
                        mma16816(t4, pH[rb][1][0], pH[rb][1][1], pH[rb][1][2], pH[rb][1][3], gl[2], gl[3]);
                        acc2[rb][nt].x += s0[rb] * t4.x;
                        acc2[rb][nt].y += s0[rb] * t4.y;
                        acc2[rb][nt].z += s1[rb] * t4.z;
                        acc2[rb][nt].w += s1[rb] * t4.w;
                    }
                }
            }
        }
    }

    // ---- R epilogue: split -> RS [2][128][40]h (aliases P1S) ----
    __syncthreads();   // everyone done reading P1S before overwrite (RS aliases it)
    #pragma unroll
    for (int rb = 0; rb < 2; rb++)
        #pragma unroll
        for (int nt = 0; nt < 4; nt++) {
            int c0 = nt * 8 + q * 2;
            u32 hi, lo;
            split2h(acc2[rb][nt].x, acc2[rb][nt].y, hi, lo);
            *(u32*)(sm + OFF_RS + (rA[rb] * 40 + c0) * 2) = hi;
            *(u32*)(sm + OFF_RS + 10240 + (rA[rb] * 40 + c0) * 2) = lo;
            split2h(acc2[rb][nt].z, acc2[rb][nt].w, hi, lo);
            *(u32*)(sm + OFF_RS + (rB[rb] * 40 + c0) * 2) = hi;
            *(u32*)(sm + OFF_RS + 10240 + (rB[rb] * 40 + c0) * 2) = lo;
        }
    __syncthreads();   // RS visible; GB region free

    // ================= Phase 3: Out = R @ Uo^T, Uo staged per 128-o half =================
    u32 rH[2][2][4], rL[2][2][4];
    #pragma unroll
    for (int rb = 0; rb < 2; rb++)
        #pragma unroll
        for (int ks = 0; ks < 2; ks++) {
            const int kk = ks * 16 + q * 2;
            rH[rb][ks][0] = *(u32*)(sm + OFF_RS + (rA[rb] * 40 + kk) * 2);
            rH[rb][ks][1] = *(u32*)(sm + OFF_RS + (rB[rb] * 40 + kk) * 2);
            rH[rb][ks][2] = *(u32*)(sm + OFF_RS + (rA[rb] * 40 + kk + 8) * 2);
            rH[rb][ks][3] = *(u32*)(sm + OFF_RS + (rB[rb] * 40 + kk + 8) * 2);
            rL[rb][ks][0] = *(u32*)(sm + OFF_RS + 10240 + (rA[rb] * 40 + kk) * 2);
            rL[rb][ks][1] = *(u32*)(sm + OFF_RS + 10240 + (rB[rb] * 40 + kk) * 2);
            rL[rb][ks][2] = *(u32*)(sm + OFF_RS + 10240 + (rA[rb] * 40 + kk + 8) * 2);
            rL[rb][ks][3] = *(u32*)(sm + OFF_RS + 10240 + (rB[rb] * 40 + kk + 8) * 2);
        }

    for (int h = 0; h < 2; h++) {
        if (h) __syncthreads();               // previous half's reads done
        #pragma unroll 1
        for (int i = tid; i < 1280; i += NTH) {
            int sp = (i >= 640) ? 1 : 0;
            int j = i - sp * 640;
            cpa16(sb + OFF_UO + sp * 10240 + j * 16,
                  g_UOS + (size_t)sp * 5120 + (size_t)h * 2560 + (size_t)j * 4);
        }
        CPA_COMMIT;
        CPA_WAIT0;
        __syncthreads();

        const u32 ub3 = sb + OFF_UO + lm40;
        #pragma unroll 4
        for (int nt = 0; nt < 16; nt++) {
            u32 uh[4], ul[4];
            u32 ua = ub3 + (u32)(nt * 640);
            ldmx4(uh[0], uh[1], uh[2], uh[3], ua);
            ldmx4(ul[0], ul[1], ul[2], ul[3], ua + 10240);
            const int o0 = h * 128 + nt * 8 + q * 2;
            #pragma unroll
            for (int rb = 0; rb < 2; rb++) {
                float4 t = make_float4(0.f, 0.f, 0.f, 0.f);
                mma16816(t, rH[rb][0][0], rH[rb][0][1], rH[rb][0][2], rH[rb][0][3], uh[0], uh[1]);
                mma16816(t, rH[rb][1][0], rH[rb][1][1], rH[rb][1][2], rH[rb][1][3], uh[2], uh[3]);
                mma16816(t, rL[rb][0][0], rL[rb][0][1], rL[rb][0][2], rL[rb][0][3], uh[0], uh[1]);
                mma16816(t, rL[rb][1][0], rL[rb][1][1], rL[rb][1][2], rL[rb][1][3], uh[2], uh[3]);
                mma16816(t, rH[rb][0][0], rH[rb][0][1], rH[rb][0][2], rH[rb][0][3], ul[0], ul[1]);
                mma16816(t, rH[rb][1][0], rH[rb][1][1], rH[rb][1][2], rH[rb][1][3], ul[2], ul[3]);
                if (okA[rb])
                    *(float2*)(out + (size_t)(base + rA[rb]) * 256 + o0) = make_float2(t.x, t.y);
                if (okB[rb])
                    *(float2*)(out + (size_t)(base + rB[rb]) * 256 + o0) = make_float2(t.z, t.w);
            }
        }
    }
}

extern "C" void kernel_launch(void* const* d_in, const int* in_sizes, int n_in,
                              void* d_out, int out_size)
{
    const float* X  = (const float*)d_in[0];   // neighbour_states
    const float* Gg = (const float*)d_in[1];   // G
    const float* Uw = (const float*)d_in[2];   // U_w
    const float* Ub = (const float*)d_in[3];   // U_b
    const float* Uo = (const float*)d_in[4];   // U_out
    float* outp = (float*)d_out;

    int nNodes = in_sizes[0] / 512;

    prep_kernel<<<32, 256>>>(Uw, Gg, Uo);

    cudaFuncSetAttribute(hosvd_mma,
                         cudaFuncAttributeMaxDynamicSharedMemorySize, SMEM_TOTAL);
    int grid = (nNodes + TN - 1) / TN;
    hosvd_mma<<<grid, NTH, SMEM_TOTAL>>>(X, Ub, outp, nNodes);
}

// round 8
// speedup vs baseline: 3.5978x; 1.0902x over previous
#include <cuda_runtime.h>
#include <cstdint>

typedef uint32_t u32;

#define TN   128
#define NTH  128

// ---------- global fp16-split weight images (written by prep kernel) ----------
// UWS: [d][sp][32 r][264 halves]   -> u32[16896]
// GS : [sp][32 a][32 c][40 halves] -> u32[40960]  (lo half unused by main now)
// UOS: [sp][256 o][40 halves]      -> u32[10240]
__device__ __align__(16) u32 g_UWS[16896];
__device__ __align__(16) u32 g_GS[40960];
__device__ __align__(16) u32 g_UOS[10240];

// ---------- smem byte offsets ----------
#define OFF_P0   0            // fp32 [128][33] = 16896
#define OFF_P1S  16896        // [2 sp][128][34]h, sp stride 8704 -> 17408
#define OFF_RS   16896        // alias (phase 3)
#define OFF_SCR  34304        // 40960-byte scratch region
#define OFF_UW   OFF_SCR      // per-d Uw image 33792
#define OFF_G    OFF_SCR      // G hi pingpong 2 x 20480 = 40960
#define OFF_UO   OFF_SCR      // full Uo image 40960
#define OFF_UB   75264        // 256 B bias
#define SMEM_TOTAL 75520      // x3 CTAs = 226560

#define P1S_A(sp,row,c) (OFF_P1S + (sp) * 8704 + ((row) * 34 + (c)) * 2)

__device__ __forceinline__ u32 s2u(const void* p) {
    u32 a; asm("{.reg .u64 t; cvta.to.shared.u64 t,%1; cvt.u32.u64 %0,t;}" : "=r"(a) : "l"(p));
    return a;
}
__device__ __forceinline__ void cpa16(u32 dst, const void* src) {
    asm volatile("cp.async.ca.shared.global [%0],[%1],16;" :: "r"(dst), "l"(src));
}
#define CPA_COMMIT asm volatile("cp.async.commit_group;" ::: "memory")
#define CPA_WAIT0  asm volatile("cp.async.wait_group 0;" ::: "memory")

__device__ __forceinline__ void ldmx4(u32& r0, u32& r1, u32& r2, u32& r3, u32 addr) {
    asm volatile("ldmatrix.sync.aligned.m8n8.x4.shared.b16 {%0,%1,%2,%3},[%4];"
                 : "=r"(r0), "=r"(r1), "=r"(r2), "=r"(r3) : "r"(addr));
}

// pack two f32 -> f16x2 (flo -> bits[15:0])
__device__ __forceinline__ u32 pkh(float flo, float fhi) {
    u32 r; asm("cvt.rn.f16x2.f32 %0,%1,%2;" : "=r"(r) : "f"(fhi), "f"(flo)); return r;
}
__device__ __forceinline__ void uph(u32 p, float& flo, float& fhi) {
    asm("{.reg .f16 a,b; mov.b32 {a,b},%2; cvt.f32.f16 %0,a; cvt.f32.f16 %1,b;}"
        : "=f"(flo), "=f"(fhi) : "r"(p));
}
__device__ __forceinline__ void split2h(float x, float y, u32& hi, u32& lo) {
    hi = pkh(x, y);
    float hx, hy; uph(hi, hx, hy);
    lo = pkh(x - hx, y - hy);
}
__device__ __forceinline__ void mma16816(float4& d, u32 a0, u32 a1, u32 a2, u32 a3,
                                         u32 b0, u32 b1) {
    asm volatile(
        "mma.sync.aligned.m16n8k16.row.col.f32.f16.f16.f32 "
        "{%0,%1,%2,%3},{%4,%5,%6,%7},{%8,%9},{%0,%1,%2,%3};"
        : "+f"(d.x), "+f"(d.y), "+f"(d.z), "+f"(d.w)
        : "r"(a0), "r"(a1), "r"(a2), "r"(a3), "r"(b0), "r"(b1));
}

// ================= prep: split weights to fp16 hi/lo global images =================
__global__ void prep_kernel(const float* __restrict__ Uw,
                            const float* __restrict__ Gg,
                            const float* __restrict__ Uo)
{
    for (int task = blockIdx.x * blockDim.x + threadIdx.x; task < 28672;
         task += gridDim.x * blockDim.x) {
        if (task < 8192) {                       // UWS: d(2) x r(32) x ip(128)
            int d = task >> 12, r = (task >> 7) & 31, ip = task & 127;
            float x0 = Uw[d * 8192 + r * 256 + 2 * ip];
            float x1 = Uw[d * 8192 + r * 256 + 2 * ip + 1];
            u32 hi, lo; split2h(x0, x1, hi, lo);
            g_UWS[((d * 2 + 0) * 32 + r) * 132 + ip] = hi;
            g_UWS[((d * 2 + 1) * 32 + r) * 132 + ip] = lo;
        } else if (task < 24576) {               // GS: a(32) x c(32) x bp(16)
            int t = task - 8192;
            int a = t >> 9, c = (t >> 4) & 31, bp = t & 15;
            float x0 = Gg[a * 1024 + (2 * bp) * 32 + c];
            float x1 = Gg[a * 1024 + (2 * bp + 1) * 32 + c];
            u32 hi, lo; split2h(x0, x1, hi, lo);
            g_GS[((0 * 32 + a) * 32 + c) * 20 + bp] = hi;
            g_GS[((1 * 32 + a) * 32 + c) * 20 + bp] = lo;
        } else {                                 // UOS: o(256) x cp(16)
            int t = task - 24576;
            int o = t >> 4, cp = t & 15;
            float x0 = Uo[o * 32 + 2 * cp];
            float x1 = Uo[o * 32 + 2 * cp + 1];
            u32 hi, lo; split2h(x0, x1, hi, lo);
            g_UOS[(0 * 256 + o) * 20 + cp] = hi;
            g_UOS[(1 * 256 + o) * 20 + cp] = lo;
        }
    }
}

// ================= main: 4 warps, m32 per warp (two m16 blocks) =================
__global__ __launch_bounds__(NTH, 3)
void hosvd_mma(const float* __restrict__ X,    // [N][2][256]
               const float* __restrict__ Ub,   // [2][32]
               float* __restrict__ out,        // [N][256]
               int nN)
{
    extern __shared__ __align__(16) char sm[];
    const u32 sb   = s2u(sm);
    const int tid  = threadIdx.x;
    const int lane = tid & 31;
    const int q    = lane & 3;
    const int cg   = lane >> 2;
    const int rw   = (tid >> 5) * 32;                 // warp row base
    const int base = blockIdx.x * TN;

    const int lm8 = lane & 7, lmm = lane >> 3;
    const u32 lmW  = (u32)(lm8 * 528 + lmm * 16);     // Uw image, 264h rows
    const u32 lm40 = (u32)(lm8 * 80 + lmm * 16);      // 40h rows (G/Uo)

    int  rA[2], rB[2];
    bool okA[2], okB[2];
    #pragma unroll
    for (int rb = 0; rb < 2; rb++) {
        rA[rb] = rw + rb * 16 + cg;
        rB[rb] = rA[rb] + 8;
        okA[rb] = (base + rA[rb]) < nN;
        okB[rb] = (base + rB[rb]) < nN;
    }

    if (tid < 64) *(float*)(sm + OFF_UB + tid * 4) = Ub[tid];

    // ================= Phase 1: P = [X_d @ Uw_d^T] =================
    for (int d = 0; d < 2; d++) {
        __syncthreads();                      // previous users of UW region done
        for (int i = tid; i < 2112; i += NTH)
            cpa16(sb + OFF_UW + i * 16,
                  (const char*)g_UWS + (size_t)d * 33792 + (size_t)i * 16);
        CPA_COMMIT;

        float4 acc[2][4];
        #pragma unroll
        for (int rb = 0; rb < 2; rb++)
            #pragma unroll
            for (int nt = 0; nt < 4; nt++) acc[rb][nt] = make_float4(0.f, 0.f, 0.f, 0.f);

        const float* xb = X + (size_t)base * 512 + d * 256;

        for (int ch = 0; ch < 4; ch++) {
            const int c4 = ch * 64;
            #pragma unroll
            for (int ksh = 0; ksh < 2; ksh++) {
                u32 xh[2][2][4], xl[2][2][4];
                #pragma unroll
                for (int rb = 0; rb < 2; rb++)
                    #pragma unroll
                    for (int ks2 = 0; ks2 < 2; ks2++) {
                        const int kk = c4 + ksh * 32 + ks2 * 16 + q * 2;
                        float2 v00 = okA[rb] ? *(const float2*)(xb + (size_t)rA[rb] * 512 + kk)
                                             : make_float2(0.f, 0.f);
                        float2 v10 = okB[rb] ? *(const float2*)(xb + (size_t)rB[rb] * 512 + kk)
                                             : make_float2(0.f, 0.f);
                        float2 v01 = okA[rb] ? *(const float2*)(xb + (size_t)rA[rb] * 512 + kk + 8)
                                             : make_float2(0.f, 0.f);
                        float2 v11 = okB[rb] ? *(const float2*)(xb + (size_t)rB[rb] * 512 + kk + 8)
                                             : make_float2(0.f, 0.f);
                        split2h(v00.x, v00.y, xh[rb][ks2][0], xl[rb][ks2][0]);
                        split2h(v10.x, v10.y, xh[rb][ks2][1], xl[rb][ks2][1]);
                        split2h(v01.x, v01.y, xh[rb][ks2][2], xl[rb][ks2][2]);
                        split2h(v11.x, v11.y, xh[rb][ks2][3], xl[rb][ks2][3]);
                    }
                if (ch == 0 && ksh == 0) { CPA_WAIT0; __syncthreads(); }

                const u32 wb = sb + OFF_UW + lmW + (u32)((c4 + ksh * 32) * 2);
                #pragma unroll
                for (int nt = 0; nt < 4; nt++) {
                    u32 bh[4], bl[4];
                    u32 a0 = wb + (u32)(nt * 4224);
                    ldmx4(bh[0], bh[1], bh[2], bh[3], a0);
                    ldmx4(bl[0], bl[1], bl[2], bl[3], a0 + 16896);
                    #pragma unroll
                    for (int rb = 0; rb < 2; rb++)
                        #pragma unroll
                        for (int ks2 = 0; ks2 < 2; ks2++) {
                            mma16816(acc[rb][nt],
                                     xh[rb][ks2][0], xh[rb][ks2][1], xh[rb][ks2][2], xh[rb][ks2][3],
                                     bh[ks2 * 2], bh[ks2 * 2 + 1]);
                            mma16816(acc[rb][nt],
                                     xl[rb][ks2][0], xl[rb][ks2][1], xl[rb][ks2][2], xl[rb][ks2][3],
                                     bh[ks2 * 2], bh[ks2 * 2 + 1]);
                            mma16816(acc[rb][nt],
                                     xh[rb][ks2][0], xh[rb][ks2][1], xh[rb][ks2][2], xh[rb][ks2][3],
                                     bl[ks2 * 2], bl[ks2 * 2 + 1]);
                        }
                }
            }
        }

        // epilogue for this d: +bias; d=0 -> P0 fp32; d=1 -> P1S split
        float* P0f = (float*)(sm + OFF_P0);
        #pragma unroll
        for (int rb = 0; rb < 2; rb++)
            #pragma unroll
            for (int nt = 0; nt < 4; nt++) {
                int c0 = nt * 8 + q * 2;
                float bx = *(float*)(sm + OFF_UB + (d * 32 + c0) * 4);
                float by = *(float*)(sm + OFF_UB + (d * 32 + c0 + 1) * 4);
                float px0 = acc[rb][nt].x + bx, py0 = acc[rb][nt].y + by;
                float px1 = acc[rb][nt].z + bx, py1 = acc[rb][nt].w + by;
                if (d == 0) {
                    P0f[rA[rb] * 33 + c0] = px0;  P0f[rA[rb] * 33 + c0 + 1] = py0;
                    P0f[rB[rb] * 33 + c0] = px1;  P0f[rB[rb] * 33 + c0 + 1] = py1;
                } else {
                    u32 hi, lo;
                    split2h(px0, py0, hi, lo);
                    *(u32*)(sm + P1S_A(0, rA[rb], c0)) = hi;
                    *(u32*)(sm + P1S_A(1, rA[rb], c0)) = lo;
                    split2h(px1, py1, hi, lo);
                    *(u32*)(sm + P1S_A(0, rB[rb], c0)) = hi;
                    *(u32*)(sm + P1S_A(1, rB[rb], c0)) = lo;
                }
            }
    }
    __syncthreads();   // P visible; UW region free

    // ================= Phase 2: r[n,c] = sum_a p0[n,a] * (p1 @ Ghi[a]^T) =================
    float4 acc2[2][4];
    #pragma unroll
    for (int rb = 0; rb < 2; rb++)
        #pragma unroll
        for (int nt = 0; nt < 4; nt++) acc2[rb][nt] = make_float4(0.f, 0.f, 0.f, 0.f);
    {
        u32 pH[2][2][4], pL[2][2][4];          // [rb][ks][frag]
        #pragma unroll
        for (int rb = 0; rb < 2; rb++)
            #pragma unroll
            for (int ks = 0; ks < 2; ks++) {
                const int kk = ks * 16 + q * 2;
                pH[rb][ks][0] = *(u32*)(sm + P1S_A(0, rA[rb], kk));
                pH[rb][ks][1] = *(u32*)(sm + P1S_A(0, rB[rb], kk));
                pH[rb][ks][2] = *(u32*)(sm + P1S_A(0, rA[rb], kk + 8));
                pH[rb][ks][3] = *(u32*)(sm + P1S_A(0, rB[rb], kk + 8));
                pL[rb][ks][0] = *(u32*)(sm + P1S_A(1, rA[rb], kk));
                pL[rb][ks][1] = *(u32*)(sm + P1S_A(1, rB[rb], kk));
                pL[rb][ks][2] = *(u32*)(sm + P1S_A(1, rA[rb], kk + 8));
                pL[rb][ks][3] = *(u32*)(sm + P1S_A(1, rB[rb], kk + 8));
            }
        const float* P0f = (const float*)(sm + OFF_P0);

        // prefetch G chunk 0 (8 a's, hi only): 1280 x 16B = 20480 B
        #pragma unroll 1
        for (int i = tid; i < 1280; i += NTH)
            cpa16(sb + OFF_G + i * 16, g_GS + (size_t)i * 4);
        CPA_COMMIT;

        for (int cc = 0; cc < 4; cc++) {
            CPA_WAIT0;
            __syncthreads();
            if (cc < 3) {
                int pp = (cc + 1) & 1;
                #pragma unroll 1
                for (int i = tid; i < 1280; i += NTH)
                    cpa16(sb + OFF_G + pp * 20480 + i * 16,
                          g_GS + (size_t)(cc + 1) * 5120 + (size_t)i * 4);
                CPA_COMMIT;
            }
            const u32 gb = sb + OFF_G + (u32)((cc & 1) * 20480) + lm40;
            #pragma unroll
            for (int al = 0; al < 8; al++) {
                const int a = cc * 8 + al;
                float s0[2], s1[2];
                #pragma unroll
                for (int rb = 0; rb < 2; rb++) {
                    s0[rb] = P0f[rA[rb] * 33 + a];
                    s1[rb] = P0f[rB[rb] * 33 + a];
                }
                #pragma unroll
                for (int nt = 0; nt < 4; nt++) {
                    u32 gh[4];
                    ldmx4(gh[0], gh[1], gh[2], gh[3], gb + (u32)(al * 2560 + nt * 640));
                    #pragma unroll
                    for (int rb = 0; rb < 2; rb++) {
                        float4 t4 = make_float4(0.f, 0.f, 0.f, 0.f);
                        mma16816(t4, pH[rb][0][0], pH[rb][0][1], pH[rb][0][2], pH[rb][0][3], gh[0], gh[1]);
                        mma16816(t4, pH[rb][1][0], pH[rb][1][1], pH[rb][1][2], pH[rb][1][3], gh[2], gh[3]);
                        mma16816(t4, pL[rb][0][0], pL[rb][0][1], pL[rb][0][2], pL[rb][0][3], gh[0], gh[1]);
                        mma16816(t4, pL[rb][1][0], pL[rb][1][1], pL[rb][1][2], pL[rb][1][3], gh[2], gh[3]);
                        acc2[rb][nt].x += s0[rb] * t4.x;
                        acc2[rb][nt].y += s0[rb] * t4.y;
                        acc2[rb][nt].z += s1[rb] * t4.z;
                        acc2[rb][nt].w += s1[rb] * t4.w;
                    }
                }
            }
        }
    }

    // ---- R epilogue: split -> RS (aliases P1S) ----
    __syncthreads();   // all warps done with P1S reads + final G chunk
    #pragma unroll
    for (int rb = 0; rb < 2; rb++)
        #pragma unroll
        for (int nt = 0; nt < 4; nt++) {
            int c0 = nt * 8 + q * 2;
            u32 hi, lo;
            split2h(acc2[rb][nt].x, acc2[rb][nt].y, hi, lo);
            *(u32*)(sm + P1S_A(0, rA[rb], c0)) = hi;
            *(u32*)(sm + P1S_A(1, rA[rb], c0)) = lo;
            split2h(acc2[rb][nt].z, acc2[rb][nt].w, hi, lo);
            *(u32*)(sm + P1S_A(0, rB[rb], c0)) = hi;
            *(u32*)(sm + P1S_A(1, rB[rb], c0)) = lo;
        }
    __syncthreads();   // RS visible; G region free

    // ---- stage full Uo image (aliases G region) ----
    #pragma unroll 1
    for (int i = tid; i < 2560; i += NTH)
        cpa16(sb + OFF_UO + i * 16, g_UOS + (size_t)i * 4);
    CPA_COMMIT;

    // preload R fragments while Uo flies
    u32 rH[2][2][4], rL[2][2][4];
    #pragma unroll
    for (int rb = 0; rb < 2; rb++)
        #pragma unroll
        for (int ks = 0; ks < 2; ks++) {
            const int kk = ks * 16 + q * 2;
            rH[rb][ks][0] = *(u32*)(sm + P1S_A(0, rA[rb], kk));
            rH[rb][ks][1] = *(u32*)(sm + P1S_A(0, rB[rb], kk));
            rH[rb][ks][2] = *(u32*)(sm + P1S_A(0, rA[rb], kk + 8));
            rH[rb][ks][3] = *(u32*)(sm + P1S_A(0, rB[rb], kk + 8));
            rL[rb][ks][0] = *(u32*)(sm + P1S_A(1, rA[rb], kk));
            rL[rb][ks][1] = *(u32*)(sm + P1S_A(1, rB[rb], kk));
            rL[rb][ks][2] = *(u32*)(sm + P1S_A(1, rA[rb], kk + 8));
            rL[rb][ks][3] = *(u32*)(sm + P1S_A(1, rB[rb], kk + 8));
        }
    CPA_WAIT0;
    __syncthreads();

    // ================= Phase 3: Out = R @ Uo^T (full Uo resident) =================
    const u32 ub3 = sb + OFF_UO + lm40;
    #pragma unroll 4
    for (int nt = 0; nt < 32; nt++) {
        u32 uh[4], ul[4];
        u32 ua = ub3 + (u32)(nt * 640);
        ldmx4(uh[0], uh[1], uh[2], uh[3], ua);
        ldmx4(ul[0], ul[1], ul[2], ul[3], ua + 20480);
        const int o0 = nt * 8 + q * 2;
        #pragma unroll
        for (int rb = 0; rb < 2; rb++) {
            float4 t = make_float4(0.f, 0.f, 0.f, 0.f);
            mma16816(t, rH[rb][0][0], rH[rb][0][1], rH[rb][0][2], rH[rb][0][3], uh[0], uh[1]);
            mma16816(t, rH[rb][1][0], rH[rb][1][1], rH[rb][1][2], rH[rb][1][3], uh[2], uh[3]);
            mma16816(t, rL[rb][0][0], rL[rb][0][1], rL[rb][0][2], rL[rb][0][3], uh[0], uh[1]);
            mma16816(t, rL[rb][1][0], rL[rb][1][1], rL[rb][1][2], rL[rb][1][3], uh[2], uh[3]);
            mma16816(t, rH[rb][0][0], rH[rb][0][1], rH[rb][0][2], rH[rb][0][3], ul[0], ul[1]);
            mma16816(t, rH[rb][1][0], rH[rb][1][1], rH[rb][1][2], rH[rb][1][3], ul[2], ul[3]);
            if (okA[rb])
                *(float2*)(out + (size_t)(base + rA[rb]) * 256 + o0) = make_float2(t.x, t.y);
            if (okB[rb])
                *(float2*)(out + (size_t)(base + rB[rb]) * 256 + o0) = make_float2(t.z, t.w);
        }
    }
}

extern "C" void kernel_launch(void* const* d_in, const int* in_sizes, int n_in,
                              void* d_out, int out_size)
{
    const float* X  = (const float*)d_in[0];   // neighbour_states
    const float* Gg = (const float*)d_in[1];   // G
    const float* Uw = (const float*)d_in[2];   // U_w
    const float* Ub = (const float*)d_in[3];   // U_b
    const float* Uo = (const float*)d_in[4];   // U_out
    float* outp = (float*)d_out;

    int nNodes = in_sizes[0] / 512;

    prep_kernel<<<32, 256>>>(Uw, Gg, Uo);

    cudaFuncSetAttribute(hosvd_mma,
                         cudaFuncAttributeMaxDynamicSharedMemorySize, SMEM_TOTAL);
    int grid = (nNodes + TN - 1) / TN;
    hosvd_mma<<<grid, NTH, SMEM_TOTAL>>>(X, Ub, outp, nNodes);
}